// round 15
// baseline (speedup 1.0000x reference)
#include <cuda_runtime.h>
#include <cuda_bf16.h>
#include <cstdint>
#include <math.h>

// ---------------------------------------------------------------------------
// Static device scratch (no allocation allowed)
// ---------------------------------------------------------------------------
__device__ __align__(128) float g_H3[2u * 4096u * 4096u];   // 134 MB (dx-summed Gram lv3)
__device__ __align__(128) float g_H2[2u * 1024u * 1024u];
__device__ __align__(128) float g_H1[2u * 256u * 256u];
__device__ __align__(128) float g_R2[2u * 1024u * 1024u];
__device__ __align__(128) float g_R1[2u * 256u * 256u];
__device__ __align__(128) float g_R2v[2u * 4096u * 1024u];  // vertical x4 of R2
__device__ __align__(128) float g_R1v[2u * 4096u * 256u];   // vertical x16 of R1
__device__ __align__(128) float g_T3[2u * 4096u * 256u];    // ref3 in HWC
__device__ __align__(128) float g_T2[2u * 16384u * 128u];   // ref2 in HWC
__device__ __align__(128) float g_T1[2u * 65536u * 64u];    // ref1 in HWC
__device__ __align__(128) float g_invL3[2 * 4096];
__device__ __align__(128) float g_invR3[2 * 4096];
__device__ __align__(128) float g_invL2[2 * 1024];
__device__ __align__(128) float g_invR2[2 * 1024];
__device__ __align__(128) float g_invL1[2 * 256];
__device__ __align__(128) float g_invR1[2 * 256];
__device__ __align__(128) int4   g_i4[4096];
__device__ __align__(128) float4 g_w4[4096];
__device__ __align__(128) int4   g_i16[4096];
__device__ __align__(128) float4 g_w16[4096];
__device__ __align__(128) unsigned long long g_key[2 * 4096];
__device__ __align__(128) int g_arg[2 * 4096];

// ---------------------------------------------------------------------------
// Packed f32x2 FMA helpers (sm_103a; 2 independent IEEE rn FMAs per instr)
// ---------------------------------------------------------------------------
__device__ __forceinline__ unsigned long long pack2(float lo, float hi) {
    unsigned long long r;
    asm("mov.b64 %0, {%1, %2};" : "=l"(r) : "f"(lo), "f"(hi));
    return r;
}
__device__ __forceinline__ void ffma2(unsigned long long& d,
                                      unsigned long long a, unsigned long long b) {
    asm("fma.rn.f32x2 %0, %1, %2, %0;" : "+l"(d) : "l"(a), "l"(b));
}
__device__ __forceinline__ float2 unpack2(unsigned long long v) {
    float lo, hi;
    asm("mov.b64 {%0, %1}, %2;" : "=f"(lo), "=f"(hi) : "l"(v));
    return make_float2(lo, hi);
}

// ---------------------------------------------------------------------------
// Bicubic weight (PyTorch a=-0.75)
// ---------------------------------------------------------------------------
__device__ __forceinline__ float cubic_w(float x) {
    const float a = -0.75f;
    float ax = fabsf(x);
    float ax2 = ax * ax, ax3 = ax2 * ax;
    float w1 = (a + 2.0f) * ax3 - (a + 3.0f) * ax2 + 1.0f;
    float w2 = ((a * ax3 - 5.0f * a * ax2) + 8.0f * a * ax) - 4.0f * a;
    return (ax <= 1.0f) ? w1 : ((ax < 2.0f) ? w2 : 0.0f);
}

// ---------------------------------------------------------------------------
// prep: block 0..11 -> sumsq + 3x3 zero-pad box norm for 6 tensor-batches
//       block 12    -> bicubic tables,  block 13 -> argmax key reset
// ---------------------------------------------------------------------------
__global__ void __launch_bounds__(1024) prep_kernel(
    const float* __restrict__ lrsr3, const float* __restrict__ refsr3,
    const float* __restrict__ lrsr2, const float* __restrict__ refsr2,
    const float* __restrict__ lrsr1, const float* __restrict__ refsr1)
{
    int bid = blockIdx.x;
    int t = threadIdx.x;
    if (bid < 12) {
        int ti = bid >> 1, b = bid & 1;
        const float* src; float* dst; int C, W;
        switch (ti) {
            case 0: src = lrsr3;  dst = g_invL3; C = 64;  W = 64; break;
            case 1: src = refsr3; dst = g_invR3; C = 64;  W = 64; break;
            case 2: src = lrsr2;  dst = g_invL2; C = 128; W = 32; break;
            case 3: src = refsr2; dst = g_invR2; C = 128; W = 32; break;
            case 4: src = lrsr1;  dst = g_invL1; C = 256; W = 16; break;
            default:src = refsr1; dst = g_invR1; C = 256; W = 16; break;
        }
        int HW = W * W, P4 = HW >> 2;
        int nstr = 1024 / P4;                 // 1, 4, 16
        int cper = C / nstr;                  // 64, 32, 16
        __shared__ float4 s4[1024];
        __shared__ float sP[4096];
        int p4 = t & (P4 - 1), st = t / P4;
        const float* xb = src + (long)b * C * HW;
        float4 acc = make_float4(0.f, 0.f, 0.f, 0.f);
        int cs = st * cper;
        for (int c = cs; c < cs + cper; c++) {
            float4 v = *(const float4*)(xb + (long)c * HW + 4 * p4);
            acc.x += v.x * v.x; acc.y += v.y * v.y;
            acc.z += v.z * v.z; acc.w += v.w * v.w;
        }
        s4[t] = acc;
        __syncthreads();
        if (t < P4) {
            float4 r = s4[t];
            for (int k = 1; k < nstr; k++) {
                float4 v = s4[t + k * P4];
                r.x += v.x; r.y += v.y; r.z += v.z; r.w += v.w;
            }
            *(float4*)&sP[4 * t] = r;
        }
        __syncthreads();
        for (int p = t; p < HW; p += 1024) {
            int py = p / W, px = p - py * W;
            float s = 0.0f;
            for (int dy = -1; dy <= 1; dy++) {
                int qy = py + dy;
                if (qy < 0 || qy >= W) continue;
                for (int dx = -1; dx <= 1; dx++) {
                    int qx = px + dx;
                    if (qx < 0 || qx >= W) continue;
                    s += sP[qy * W + qx];
                }
            }
            dst[b * HW + p] = 1.0f / fmaxf(sqrtf(s), 1e-12f);
        }
    } else if (bid == 12) {
        for (int o = t; o < 4096; o += 1024) {
            { // scale 4 (n = 1024)
                float src = (o + 0.5f) / 4.0f - 0.5f;
                float f = floorf(src);
                float tt = src - f;
                int fi = (int)f;
                int4 id; float4 w;
                id.x = min(max(fi - 1, 0), 1023); id.y = min(max(fi, 0), 1023);
                id.z = min(max(fi + 1, 0), 1023); id.w = min(max(fi + 2, 0), 1023);
                w.x = cubic_w(tt + 1.0f); w.y = cubic_w(tt);
                w.z = cubic_w(tt - 1.0f); w.w = cubic_w(tt - 2.0f);
                g_i4[o] = id; g_w4[o] = w;
            }
            { // scale 16 (n = 256)
                float src = (o + 0.5f) / 16.0f - 0.5f;
                float f = floorf(src);
                float tt = src - f;
                int fi = (int)f;
                int4 id; float4 w;
                id.x = min(max(fi - 1, 0), 255); id.y = min(max(fi, 0), 255);
                id.z = min(max(fi + 1, 0), 255); id.w = min(max(fi + 2, 0), 255);
                w.x = cubic_w(tt + 1.0f); w.y = cubic_w(tt);
                w.z = cubic_w(tt - 1.0f); w.w = cubic_w(tt - 2.0f);
                g_i16[o] = id; g_w16[o] = w;
            }
        }
    } else {
        for (int o = t; o < 8192; o += 1024) g_key[o] = 0ull;
    }
}

// ---------------------------------------------------------------------------
// CHW -> HWC transpose.  grid (HW/32, C/32, B), block (32,8)
// ---------------------------------------------------------------------------
__global__ void transpose_kernel(const float* __restrict__ src, float* __restrict__ dst,
                                 int C, int HW)
{
    __shared__ float tile[32][33];
    int b = blockIdx.z;
    int hw0 = blockIdx.x * 32, c0 = blockIdx.y * 32;
    const float* s = src + (long)b * C * HW;
    float* d = dst + (long)b * HW * C;
    #pragma unroll
    for (int j = 0; j < 4; j++)
        tile[threadIdx.y + 8 * j][threadIdx.x] =
            s[(long)(c0 + threadIdx.y + 8 * j) * HW + hw0 + threadIdx.x];
    __syncthreads();
    #pragma unroll
    for (int j = 0; j < 4; j++)
        d[(long)(hw0 + threadIdx.y + 8 * j) * C + c0 + threadIdx.x] =
            tile[threadIdx.x][threadIdx.y + 8 * j];
}

// ---------------------------------------------------------------------------
// Big Gram GEMM (lv3, K=64, W=64) with fused dx-diag epilogue + FFMA2 core.
// 128x128 tile, 256 thr, 8x8/thread.  sG aliases As/Bs (epilogue-only).
// Per-batch launch (b passed as arg) to enable batch pipelining.
// ---------------------------------------------------------------------------
#define GB_SMEM (128 * 132 * 4)

__global__ void __launch_bounds__(256) gram_big_kernel(
    const float* __restrict__ A, const float* __restrict__ B,
    float* __restrict__ H, int b)
{
    const int N = 4096, K = 64, W = 64;
    extern __shared__ float sh[];
    float* As = sh;                 // [16][128]
    float* Bs = sh + 16 * 128;      // [16][128]
    float* sG = sh;                 // [128][132]  (reused after mainloop)

    const float* Ab = A + (long)b * K * N;
    const float* Bb = B + (long)b * K * N;
    float* Hb = H + (long)b * N * N;

    int t = threadIdx.x;
    int tx = t & 15, ty = t >> 4;
    int i0 = blockIdx.y * 128, j0 = blockIdx.x * 128;
    int lr = t >> 5;             // 0..7
    int lc = (t & 31) * 4;       // 0..124

    unsigned long long acc2[8][4];
    #pragma unroll
    for (int u = 0; u < 8; u++)
        #pragma unroll
        for (int v = 0; v < 4; v++) acc2[u][v] = 0ull;

    #pragma unroll
    for (int k0 = 0; k0 < K; k0 += 16) {
        *(float4*)&As[lr * 128 + lc]       = *(const float4*)&Ab[(long)(k0 + lr) * N + i0 + lc];
        *(float4*)&As[(lr + 8) * 128 + lc] = *(const float4*)&Ab[(long)(k0 + lr + 8) * N + i0 + lc];
        *(float4*)&Bs[lr * 128 + lc]       = *(const float4*)&Bb[(long)(k0 + lr) * N + j0 + lc];
        *(float4*)&Bs[(lr + 8) * 128 + lc] = *(const float4*)&Bb[(long)(k0 + lr + 8) * N + j0 + lc];
        __syncthreads();
        #pragma unroll
        for (int kk = 0; kk < 16; kk++) {
            float4 a0 = *(float4*)&As[kk * 128 + ty * 8];
            float4 a1 = *(float4*)&As[kk * 128 + ty * 8 + 4];
            float4 b0 = *(float4*)&Bs[kk * 128 + tx * 8];
            float4 b1 = *(float4*)&Bs[kk * 128 + tx * 8 + 4];
            unsigned long long av[8];
            av[0] = pack2(a0.x, a0.x); av[1] = pack2(a0.y, a0.y);
            av[2] = pack2(a0.z, a0.z); av[3] = pack2(a0.w, a0.w);
            av[4] = pack2(a1.x, a1.x); av[5] = pack2(a1.y, a1.y);
            av[6] = pack2(a1.z, a1.z); av[7] = pack2(a1.w, a1.w);
            unsigned long long bp[4];
            bp[0] = pack2(b0.x, b0.y); bp[1] = pack2(b0.z, b0.w);
            bp[2] = pack2(b1.x, b1.y); bp[3] = pack2(b1.z, b1.w);
            #pragma unroll
            for (int u = 0; u < 8; u++)
                #pragma unroll
                for (int v = 0; v < 4; v++)
                    ffma2(acc2[u][v], av[u], bp[v]);
        }
        __syncthreads();
    }

    // stage into sG (stride 132) — aliases As/Bs, safe after final sync above
    #pragma unroll
    for (int u = 0; u < 8; u++) {
        int r = ty * 8 + u;
        float2 p0 = unpack2(acc2[u][0]);
        float2 p1 = unpack2(acc2[u][1]);
        float2 p2 = unpack2(acc2[u][2]);
        float2 p3 = unpack2(acc2[u][3]);
        *(float4*)&sG[r * 132 + tx * 8]     = make_float4(p0.x, p0.y, p1.x, p1.y);
        *(float4*)&sG[r * 132 + tx * 8 + 4] = make_float4(p2.x, p2.y, p3.x, p3.y);
    }
    __syncthreads();

    const int wm = W - 1;
    #pragma unroll
    for (int u = 0; u < 8; u++) {
        int r = ty * 8 + u;
        int ixm = r & wm;            // i0 multiple of 128, W | 128
        float vals[8];
        #pragma unroll
        for (int v = 0; v < 8; v++) {
            int c = tx * 8 + v;
            int jxm = c & wm;
            float x = sG[r * 132 + c];
            if (ixm > 0  && jxm > 0)  x += sG[(r - 1) * 132 + (c - 1)];
            if (ixm < wm && jxm < wm) x += sG[(r + 1) * 132 + (c + 1)];
            vals[v] = x;
        }
        long row = (long)(i0 + r) * N + j0 + tx * 8;
        *(float4*)&Hb[row]     = make_float4(vals[0], vals[1], vals[2], vals[3]);
        *(float4*)&Hb[row + 4] = make_float4(vals[4], vals[5], vals[6], vals[7]);
    }
}

// ---------------------------------------------------------------------------
// Small Gram GEMM (lv2): 64x64 tile, 4x4/thread, fused dx epilogue.
// ---------------------------------------------------------------------------
__global__ void __launch_bounds__(256) gram_small_kernel(
    const float* __restrict__ A, const float* __restrict__ B,
    float* __restrict__ H, int N, int K, int W)
{
    __shared__ float As[16 * 64];
    __shared__ float Bs[16 * 64];
    __shared__ float sG[64 * 68];

    int b = blockIdx.z;
    const float* Ab = A + (long)b * K * N;
    const float* Bb = B + (long)b * K * N;
    float* Hb = H + (long)b * N * N;

    int t = threadIdx.x;
    int tx = t & 15, ty = t >> 4;
    int i0 = blockIdx.y * 64, j0 = blockIdx.x * 64;
    int lr = t >> 4;             // 0..15
    int lc = (t & 15) * 4;       // 0..60

    float acc[4][4];
    #pragma unroll
    for (int u = 0; u < 4; u++)
        #pragma unroll
        for (int v = 0; v < 4; v++) acc[u][v] = 0.0f;

    for (int k0 = 0; k0 < K; k0 += 16) {
        *(float4*)&As[lr * 64 + lc] = *(const float4*)&Ab[(long)(k0 + lr) * N + i0 + lc];
        *(float4*)&Bs[lr * 64 + lc] = *(const float4*)&Bb[(long)(k0 + lr) * N + j0 + lc];
        __syncthreads();
        #pragma unroll
        for (int kk = 0; kk < 16; kk++) {
            float4 a0 = *(float4*)&As[kk * 64 + ty * 4];
            float4 b0 = *(float4*)&Bs[kk * 64 + tx * 4];
            float a[4] = {a0.x, a0.y, a0.z, a0.w};
            float bb[4] = {b0.x, b0.y, b0.z, b0.w};
            #pragma unroll
            for (int u = 0; u < 4; u++)
                #pragma unroll
                for (int v = 0; v < 4; v++) acc[u][v] += a[u] * bb[v];
        }
        __syncthreads();
    }

    #pragma unroll
    for (int u = 0; u < 4; u++) {
        int r = ty * 4 + u;
        *(float4*)&sG[r * 68 + tx * 4] = make_float4(acc[u][0], acc[u][1], acc[u][2], acc[u][3]);
    }
    __syncthreads();

    int wm = W - 1;
    #pragma unroll
    for (int u = 0; u < 4; u++) {
        int r = ty * 4 + u;
        int ixm = r & wm;
        float vals[4];
        #pragma unroll
        for (int v = 0; v < 4; v++) {
            int c = tx * 4 + v;
            int jxm = c & wm;
            float x = sG[r * 68 + c];
            if (ixm > 0  && jxm > 0)  x += sG[(r - 1) * 68 + (c - 1)];
            if (ixm < wm && jxm < wm) x += sG[(r + 1) * 68 + (c + 1)];
            vals[v] = x;
        }
        long row = (long)(i0 + r) * N + j0 + tx * 4;
        *(float4*)&Hb[row] = make_float4(vals[0], vals[1], vals[2], vals[3]);
    }
}

// ---------------------------------------------------------------------------
// Tiny Gram GEMM (lv1: N=256, K=256, W=16): 32x32 tile, 2x2/thread -> 128 blocks
// ---------------------------------------------------------------------------
__global__ void __launch_bounds__(256) gram_tiny_kernel(
    const float* __restrict__ A, const float* __restrict__ B,
    float* __restrict__ H)
{
    const int N = 256, K = 256, W = 16;
    __shared__ float As[16 * 32];
    __shared__ float Bs[16 * 32];
    __shared__ float sG[32 * 36];

    int b = blockIdx.z;
    const float* Ab = A + (long)b * K * N;
    const float* Bb = B + (long)b * K * N;
    float* Hb = H + (long)b * N * N;

    int t = threadIdx.x;
    int tx = t & 15, ty = t >> 4;
    int i0 = blockIdx.y * 32, j0 = blockIdx.x * 32;
    int lr = t >> 4;             // 0..15
    int lc = (t & 15) * 2;       // 0..30

    float acc[2][2] = {{0.f, 0.f}, {0.f, 0.f}};

    for (int k0 = 0; k0 < K; k0 += 16) {
        *(float2*)&As[lr * 32 + lc] = *(const float2*)&Ab[(long)(k0 + lr) * N + i0 + lc];
        *(float2*)&Bs[lr * 32 + lc] = *(const float2*)&Bb[(long)(k0 + lr) * N + j0 + lc];
        __syncthreads();
        #pragma unroll
        for (int kk = 0; kk < 16; kk++) {
            float2 a0 = *(float2*)&As[kk * 32 + ty * 2];
            float2 b0 = *(float2*)&Bs[kk * 32 + tx * 2];
            acc[0][0] += a0.x * b0.x; acc[0][1] += a0.x * b0.y;
            acc[1][0] += a0.y * b0.x; acc[1][1] += a0.y * b0.y;
        }
        __syncthreads();
    }

    #pragma unroll
    for (int u = 0; u < 2; u++) {
        int r = ty * 2 + u;
        *(float2*)&sG[r * 36 + tx * 2] = make_float2(acc[u][0], acc[u][1]);
    }
    __syncthreads();

    const int wm = W - 1;
    #pragma unroll
    for (int u = 0; u < 2; u++) {
        int r = ty * 2 + u;
        int ixm = r & wm;
        float vals[2];
        #pragma unroll
        for (int v = 0; v < 2; v++) {
            int c = tx * 2 + v;
            int jxm = c & wm;
            float x = sG[r * 36 + c];
            if (ixm > 0  && jxm > 0)  x += sG[(r - 1) * 36 + (c - 1)];
            if (ixm < wm && jxm < wm) x += sG[(r + 1) * 36 + (c + 1)];
            vals[v] = x;
        }
        long row = (long)(i0 + r) * N + j0 + tx * 2;
        *(float2*)&Hb[row] = make_float2(vals[0], vals[1]);
    }
}

// ---------------------------------------------------------------------------
// dy-sum + normalize for lv2 (y < 1024) and lv1 (y >= 1024), one launch
// ---------------------------------------------------------------------------
__global__ void dynorm_both_kernel() {
    int b = blockIdx.z;
    int y = blockIdx.y;
    const float* Hh; float* R; const float* invR; const float* invL;
    int N, W, lw, i;
    if (y < 1024) { Hh = g_H2; R = g_R2; invR = g_invR2; invL = g_invL2; N = 1024; W = 32; lw = 5; i = y; }
    else          { Hh = g_H1; R = g_R1; invR = g_invR1; invL = g_invL1; N = 256;  W = 16; lw = 4; i = y - 1024; }
    int j = blockIdx.x * 256 + threadIdx.x;
    if (j >= N) return;
    long base = (long)b * N * N;
    const float* h = Hh + base;
    int iy = i >> lw, jy = j >> lw;
    float v = h[(long)i * N + j];
    if (iy > 0     && jy > 0)     v += h[(long)(i - W) * N + (j - W)];
    if (iy < W - 1 && jy < W - 1) v += h[(long)(i + W) * N + (j + W)];
    R[base + (long)i * N + j] = v * invR[b * N + i] * invL[b * N + j];
}

// ---------------------------------------------------------------------------
// Vertical bicubic upsample for both levels, one launch
// ---------------------------------------------------------------------------
__global__ void vup_both_kernel() {
    int b = blockIdx.z;
    int y = blockIdx.y;
    const float* R; float* V; const int4* idx; const float4* w; int Nin, io;
    if (y < 4096) { R = g_R2; V = g_R2v; idx = g_i4;  w = g_w4;  Nin = 1024; io = y; }
    else          { R = g_R1; V = g_R1v; idx = g_i16; w = g_w16; Nin = 256;  io = y - 4096; }
    int jc = blockIdx.x * 256 + threadIdx.x;
    if (jc >= Nin) return;
    const float* r = R + (long)b * Nin * Nin;
    int4 id = idx[io]; float4 ww = w[io];
    float v = ww.x * r[(long)id.x * Nin + jc]
            + ww.y * r[(long)id.y * Nin + jc]
            + ww.z * r[(long)id.z * Nin + jc]
            + ww.w * r[(long)id.w * Nin + jc];
    V[(long)b * 4096 * Nin + (long)io * Nin + jc] = v;
}

// ---------------------------------------------------------------------------
// Fused dy-sum(H3) + normalize + horizontal bicubic + split-i max/argmax.
// 4 cols/thread, 1024-col x 128-row blocks.  Per-batch launch.
// V2/V1 tap windows staged cooperatively into smem (double-buffered):
//   thread tx reads sV2[tx..tx+4] (consecutive -> conflict-free) and
//   sV1[(tx>>2)..+4] (broadcast), replacing 10 scattered LDGs per row.
// ---------------------------------------------------------------------------
__device__ __forceinline__ unsigned fkey_ord(float f) {
    unsigned u = __float_as_uint(f);
    return u ^ ((u >> 31) ? 0xFFFFFFFFu : 0x80000000u);
}
__device__ __forceinline__ unsigned long long pack_key(float v, int i) {
    return ((unsigned long long)fkey_ord(v) << 32) | (unsigned)(4095 - i);
}

__global__ void __launch_bounds__(256) fusedmax_kernel(int b) {
    int tx = threadIdx.x;
    int j0 = blockIdx.x * 1024 + tx * 4;
    int i0 = blockIdx.y * 128;
    int base2 = blockIdx.x * 256;        // V2 window base (m2 of tx=0)
    int base1 = blockIdx.x * 64;         // V1 window base

    const float* H  = g_H3  + (long)b * 4096 * 4096;
    const float* V2 = g_R2v + (long)b * 4096 * 1024;
    const float* V1 = g_R1v + (long)b * 4096 * 256;

    float4 iL = *(const float4*)&g_invL3[b * 4096 + j0];
    float iLv[4] = {iL.x, iL.y, iL.z, iL.w};
    int jy = j0 >> 6;
    bool jm = (jy > 0), jp = (jy < 63);

    int p1 = j0 & 15;
    int sel1[4];
    #pragma unroll
    for (int c = 0; c < 4; c++) sel1[c] = ((p1 + c) >= 8) ? 1 : 0;
    float4 w2[4], w1[4];
    #pragma unroll
    for (int c = 0; c < 4; c++) { w2[c] = g_w4[j0 + c]; w1[c] = g_w16[j0 + c]; }

    // clamped source indices for cooperative window loads
    int c2a = min(max(base2 - 2 + tx, 0), 1023);          // sV2[tx]
    int c2b = min(max(base2 + 254 + tx, 0), 1023);        // sV2[256+tx], tx<4
    int c1a = min(max(base1 - 2 + tx, 0), 255);           // sV1[tx], tx<68

    __shared__ float sR[128];
    __shared__ float sV2[2][260];
    __shared__ float sV1[2][68];

    if (tx < 128) sR[tx] = g_invR3[b * 4096 + i0 + tx];
    // prologue: stage row i0 into buffer 0
    {
        const float* v2r = V2 + (long)i0 * 1024;
        const float* v1r = V1 + (long)i0 * 256;
        sV2[0][tx] = v2r[c2a];
        if (tx < 4)  sV2[0][256 + tx] = v2r[c2b];
        if (tx < 68) sV1[0][tx] = v1r[c1a];
    }
    __syncthreads();

    float best[4] = {-1e30f, -1e30f, -1e30f, -1e30f};
    int bi[4] = {i0, i0, i0, i0};

    for (int ii = 0; ii < 128; ii++) {
        int i = i0 + ii;
        int cur = ii & 1, nxt = cur ^ 1;

        // prefetch next row's windows into registers (overlaps compute)
        float p2a = 0.f, p2b = 0.f, p1v = 0.f;
        if (ii < 127) {
            const float* v2n = V2 + (long)(i + 1) * 1024;
            p2a = v2n[c2a];
            if (tx < 4)  p2b = v2n[c2b];
            if (tx < 68) p1v = V1[(long)(i + 1) * 256 + c1a];
        }

        int iy = i >> 6;
        const float* hrow = H + (long)i * 4096;
        float4 x = *(const float4*)(hrow + j0);
        float xv[4] = {x.x, x.y, x.z, x.w};
        if (iy > 0 && jm) {
            float4 d = *(const float4*)(hrow - (64 * 4096) + (j0 - 64));
            xv[0] += d.x; xv[1] += d.y; xv[2] += d.z; xv[3] += d.w;
        }
        if (iy < 63 && jp) {
            float4 d = *(const float4*)(hrow + (64 * 4096) + (j0 + 64));
            xv[0] += d.x; xv[1] += d.y; xv[2] += d.z; xv[3] += d.w;
        }
        float ir = sR[ii];
        #pragma unroll
        for (int c = 0; c < 4; c++) xv[c] = xv[c] * ir * iLv[c];

        float t2[5], t1[5];
        #pragma unroll
        for (int o = 0; o < 5; o++) t2[o] = sV2[cur][tx + o];
        #pragma unroll
        for (int o = 0; o < 5; o++) t1[o] = sV1[cur][(tx >> 2) + o];

        float s2[4];
        s2[0] = w2[0].x * t2[0] + w2[0].y * t2[1] + w2[0].z * t2[2] + w2[0].w * t2[3];
        s2[1] = w2[1].x * t2[0] + w2[1].y * t2[1] + w2[1].z * t2[2] + w2[1].w * t2[3];
        s2[2] = w2[2].x * t2[1] + w2[2].y * t2[2] + w2[2].z * t2[3] + w2[2].w * t2[4];
        s2[3] = w2[3].x * t2[1] + w2[3].y * t2[2] + w2[3].z * t2[3] + w2[3].w * t2[4];

        #pragma unroll
        for (int c = 0; c < 4; c++) {
            int s = sel1[c];
            float s1 = w1[c].x * t1[s] + w1[c].y * t1[s + 1] + w1[c].z * t1[s + 2] + w1[c].w * t1[s + 3];
            float xf = (xv[c] + s2[c]) + s1;
            if (xf > best[c]) { best[c] = xf; bi[c] = i; }
        }

        // commit prefetched row to the other buffer, one barrier per iter
        if (ii < 127) {
            sV2[nxt][tx] = p2a;
            if (tx < 4)  sV2[nxt][256 + tx] = p2b;
            if (tx < 68) sV1[nxt][tx] = p1v;
        }
        __syncthreads();
    }
    #pragma unroll
    for (int c = 0; c < 4; c++)
        atomicMax(&g_key[b * 4096 + j0 + c], pack_key(best[c], bi[c]));
}

__global__ void decode_kernel(float* __restrict__ S) {
    int t = blockIdx.x * blockDim.x + threadIdx.x;
    if (t >= 8192) return;
    unsigned long long k = g_key[t];
    unsigned hu = (unsigned)(k >> 32);
    unsigned u = (hu & 0x80000000u) ? (hu ^ 0x80000000u) : (hu ^ 0xFFFFFFFFu);
    S[t] = __uint_as_float(u) / 3.0f;
    g_arg[t] = 4095 - (int)(k & 0xFFFFFFFFu);
}

// ---------------------------------------------------------------------------
// Channel-coalesced gather+fold transfer on HWC refT.
// grid (HH/32, C/32, B), block (8,32): tx = channel-group (4 ch), ty = pixel.
// ---------------------------------------------------------------------------
template<int S, int LOGH>
__global__ void __launch_bounds__(256) transfer_kernel(
    const float* __restrict__ refT, float* __restrict__ out, int C)
{
    const int Hh = 1 << LOGH;
    const int HH = Hh * Hh;
    int b = blockIdx.z;
    int p = blockIdx.x * 32 + threadIdx.y;
    int c0 = blockIdx.y * 32 + threadIdx.x * 4;

    int y = p >> LOGH, x = p & (Hh - 1);
    int yq = y / S, xq = x / S;
    int ym = y - yq * S, xm = x - xq * S;
    int ybase = yq + 1, xbase = xq + 1;
    const int* ab = g_arg + b * 4096;

    long off[9];
    #pragma unroll
    for (int dy = 0; dy < 3; dy++) {
        #pragma unroll
        for (int dx = 0; dx < 3; dx++) {
            int k = dy * 3 + dx;
            off[k] = -1;
            int ho = ybase - dy, wo = xbase - dx;
            if (ho >= 0 && ho < 64 && wo >= 0 && wo < 64) {
                int a = ab[ho * 64 + wo];
                int ryq = (a >> 6) + dy - 1;
                int rxq = (a & 63) + dx - 1;
                if (ryq >= 0 && ryq < 64 && rxq >= 0 && rxq < 64) {
                    int ry = S * ryq + ym, rx = S * rxq + xm;
                    off[k] = (long)(ry * Hh + rx) * C + c0;
                }
            }
        }
    }
    const float* rb = refT + (long)b * HH * C;
    float a0 = 0.f, a1 = 0.f, a2 = 0.f, a3 = 0.f;
    #pragma unroll
    for (int k = 0; k < 9; k++) {
        if (off[k] >= 0) {
            float4 v = *(const float4*)(rb + off[k]);
            a0 += v.x; a1 += v.y; a2 += v.z; a3 += v.w;
        }
    }
    long ob = ((long)b * C + c0) * HH + p;
    out[ob]          = a0 / 9.0f;
    out[ob + HH]     = a1 / 9.0f;
    out[ob + 2 * HH] = a2 / 9.0f;
    out[ob + 3 * HH] = a3 / 9.0f;
}

// ---------------------------------------------------------------------------
// Launch — forked streams + batch-pipelined gram_big/fusedmax.
// ---------------------------------------------------------------------------
static void* symaddr(const void* sym) {
    void* p = nullptr;
    cudaGetSymbolAddress(&p, sym);
    return p;
}

extern "C" void kernel_launch(void* const* d_in, const int* in_sizes, int n_in,
                              void* d_out, int out_size)
{
    const float* lrsr1  = (const float*)d_in[0];   // (2,256,16,16)
    const float* lrsr2  = (const float*)d_in[1];   // (2,128,32,32)
    const float* lrsr3  = (const float*)d_in[2];   // (2,64,64,64)
    const float* refsr1 = (const float*)d_in[3];
    const float* refsr2 = (const float*)d_in[4];
    const float* refsr3 = (const float*)d_in[5];
    const float* ref1   = (const float*)d_in[6];   // (2,64,256,256)
    const float* ref2   = (const float*)d_in[7];   // (2,128,128,128)
    const float* ref3   = (const float*)d_in[8];   // (2,256,64,64)

    float* out = (float*)d_out;
    float* S  = out;                         // 2*4096
    float* T3 = S + 2 * 4096;                // 2*256*64*64
    float* T2 = T3 + 2L * 256 * 64 * 64;     // 2*128*128*128
    float* T1 = T2 + 2L * 128 * 128 * 128;   // 2*64*256*256

    float* pH3 = (float*)symaddr(g_H3);
    float* pH2 = (float*)symaddr(g_H2);
    float* pH1 = (float*)symaddr(g_H1);
    float* pT3 = (float*)symaddr(g_T3);
    float* pT2 = (float*)symaddr(g_T2);
    float* pT1 = (float*)symaddr(g_T1);

    cudaFuncSetAttribute(gram_big_kernel,
                         cudaFuncAttributeMaxDynamicSharedMemorySize, GB_SMEM);

    // One-time side streams/events (host objects only; created outside capture
    // on the first, non-captured correctness call; reused identically after).
    static cudaStream_t sA = nullptr, sB = nullptr;
    static cudaEvent_t evFork = nullptr, evB0 = nullptr, evB1 = nullptr, evTrans = nullptr;
    if (sA == nullptr) {
        cudaStreamCreateWithFlags(&sA, cudaStreamNonBlocking);
        cudaStreamCreateWithFlags(&sB, cudaStreamNonBlocking);
        cudaEventCreateWithFlags(&evFork, cudaEventDisableTiming);
        cudaEventCreateWithFlags(&evB0, cudaEventDisableTiming);
        cudaEventCreateWithFlags(&evB1, cudaEventDisableTiming);
        cudaEventCreateWithFlags(&evTrans, cudaEventDisableTiming);
    }

    // Fork from the main (capture) stream
    cudaEventRecord(evFork, 0);
    cudaStreamWaitEvent(sA, evFork, 0);
    cudaStreamWaitEvent(sB, evFork, 0);

    // Branch A: big lv3 Gram per batch (FMA-bound) -> H3
    gram_big_kernel<<<dim3(32, 32), 256, GB_SMEM, sA>>>(refsr3, lrsr3, pH3, 0);
    cudaEventRecord(evB0, sA);
    gram_big_kernel<<<dim3(32, 32), 256, GB_SMEM, sA>>>(refsr3, lrsr3, pH3, 1);
    cudaEventRecord(evB1, sA);

    // Branch B: CHW -> HWC transposes (DRAM-bound)
    transpose_kernel<<<dim3(128, 8, 2),  dim3(32, 8), 0, sB>>>(ref3, pT3, 256, 4096);
    transpose_kernel<<<dim3(512, 4, 2),  dim3(32, 8), 0, sB>>>(ref2, pT2, 128, 16384);
    transpose_kernel<<<dim3(2048, 2, 2), dim3(32, 8), 0, sB>>>(ref1, pT1, 64, 65536);
    cudaEventRecord(evTrans, sB);

    // Main branch: prep -> lv2/lv1 pyramid -> vup
    prep_kernel<<<14, 1024>>>(lrsr3, refsr3, lrsr2, refsr2, lrsr1, refsr1);
    gram_small_kernel<<<dim3(16, 16, 2), 256>>>(refsr2, lrsr2, pH2, 1024, 128, 32);
    gram_tiny_kernel<<<dim3(8, 8, 2), 256>>>(refsr1, lrsr1, pH1);
    dynorm_both_kernel<<<dim3(4, 1280, 2), 256>>>();
    vup_both_kernel<<<dim3(4, 8192, 2), 256>>>();

    // Pipelined join: fusedmax(b0) overlaps gram_big(b1)
    cudaStreamWaitEvent(0, evB0, 0);
    fusedmax_kernel<<<dim3(4, 32), 256>>>(0);
    cudaStreamWaitEvent(0, evB1, 0);
    fusedmax_kernel<<<dim3(4, 32), 256>>>(1);
    decode_kernel<<<32, 256>>>(S);

    // Join B, then transfers
    cudaStreamWaitEvent(0, evTrans, 0);
    transfer_kernel<1, 6><<<dim3(128, 8, 2),  dim3(8, 32)>>>(pT3, T3, 256);
    transfer_kernel<2, 7><<<dim3(512, 4, 2),  dim3(8, 32)>>>(pT2, T2, 128);
    transfer_kernel<4, 8><<<dim3(2048, 2, 2), dim3(8, 32)>>>(pT1, T1, 64);
}

// round 16
// speedup vs baseline: 1.2133x; 1.2133x over previous
#include <cuda_runtime.h>
#include <cuda_bf16.h>
#include <cstdint>
#include <math.h>

// ---------------------------------------------------------------------------
// Static device scratch (no allocation allowed)
// ---------------------------------------------------------------------------
__device__ __align__(128) float g_H3[2u * 4096u * 4096u];   // 134 MB (dx-summed Gram lv3)
__device__ __align__(128) float g_H2[2u * 1024u * 1024u];
__device__ __align__(128) float g_H1[2u * 256u * 256u];
__device__ __align__(128) float g_R2[2u * 1024u * 1024u];
__device__ __align__(128) float g_R1[2u * 256u * 256u];
__device__ __align__(128) float g_R2v[2u * 4096u * 1024u];  // vertical x4 of R2
__device__ __align__(128) float g_R1v[2u * 4096u * 256u];   // vertical x16 of R1
__device__ __align__(128) float g_T3[2u * 4096u * 256u];    // ref3 in HWC
__device__ __align__(128) float g_T2[2u * 16384u * 128u];   // ref2 in HWC
__device__ __align__(128) float g_T1[2u * 65536u * 64u];    // ref1 in HWC
__device__ __align__(128) float g_invL3[2 * 4096];
__device__ __align__(128) float g_invR3[2 * 4096];
__device__ __align__(128) float g_invL2[2 * 1024];
__device__ __align__(128) float g_invR2[2 * 1024];
__device__ __align__(128) float g_invL1[2 * 256];
__device__ __align__(128) float g_invR1[2 * 256];
__device__ __align__(128) int4   g_i4[4096];
__device__ __align__(128) float4 g_w4[4096];
__device__ __align__(128) int4   g_i16[4096];
__device__ __align__(128) float4 g_w16[4096];
__device__ __align__(128) unsigned long long g_key[2 * 4096];
__device__ __align__(128) int g_arg[2 * 4096];

// ---------------------------------------------------------------------------
// Packed f32x2 FMA helpers (sm_103a; 2 independent IEEE rn FMAs per instr)
// ---------------------------------------------------------------------------
__device__ __forceinline__ unsigned long long pack2(float lo, float hi) {
    unsigned long long r;
    asm("mov.b64 %0, {%1, %2};" : "=l"(r) : "f"(lo), "f"(hi));
    return r;
}
__device__ __forceinline__ void ffma2(unsigned long long& d,
                                      unsigned long long a, unsigned long long b) {
    asm("fma.rn.f32x2 %0, %1, %2, %0;" : "+l"(d) : "l"(a), "l"(b));
}
__device__ __forceinline__ float2 unpack2(unsigned long long v) {
    float lo, hi;
    asm("mov.b64 {%0, %1}, %2;" : "=f"(lo), "=f"(hi) : "l"(v));
    return make_float2(lo, hi);
}

// ---------------------------------------------------------------------------
// Bicubic weight (PyTorch a=-0.75)
// ---------------------------------------------------------------------------
__device__ __forceinline__ float cubic_w(float x) {
    const float a = -0.75f;
    float ax = fabsf(x);
    float ax2 = ax * ax, ax3 = ax2 * ax;
    float w1 = (a + 2.0f) * ax3 - (a + 3.0f) * ax2 + 1.0f;
    float w2 = ((a * ax3 - 5.0f * a * ax2) + 8.0f * a * ax) - 4.0f * a;
    return (ax <= 1.0f) ? w1 : ((ax < 2.0f) ? w2 : 0.0f);
}

// ---------------------------------------------------------------------------
// prep: block 0..11 -> sumsq + 3x3 zero-pad box norm for 6 tensor-batches
//       block 12    -> bicubic tables,  block 13 -> argmax key reset
// ---------------------------------------------------------------------------
__global__ void __launch_bounds__(1024) prep_kernel(
    const float* __restrict__ lrsr3, const float* __restrict__ refsr3,
    const float* __restrict__ lrsr2, const float* __restrict__ refsr2,
    const float* __restrict__ lrsr1, const float* __restrict__ refsr1)
{
    int bid = blockIdx.x;
    int t = threadIdx.x;
    if (bid < 12) {
        int ti = bid >> 1, b = bid & 1;
        const float* src; float* dst; int C, W;
        switch (ti) {
            case 0: src = lrsr3;  dst = g_invL3; C = 64;  W = 64; break;
            case 1: src = refsr3; dst = g_invR3; C = 64;  W = 64; break;
            case 2: src = lrsr2;  dst = g_invL2; C = 128; W = 32; break;
            case 3: src = refsr2; dst = g_invR2; C = 128; W = 32; break;
            case 4: src = lrsr1;  dst = g_invL1; C = 256; W = 16; break;
            default:src = refsr1; dst = g_invR1; C = 256; W = 16; break;
        }
        int HW = W * W, P4 = HW >> 2;
        int nstr = 1024 / P4;                 // 1, 4, 16
        int cper = C / nstr;                  // 64, 32, 16
        __shared__ float4 s4[1024];
        __shared__ float sP[4096];
        int p4 = t & (P4 - 1), st = t / P4;
        const float* xb = src + (long)b * C * HW;
        float4 acc = make_float4(0.f, 0.f, 0.f, 0.f);
        int cs = st * cper;
        for (int c = cs; c < cs + cper; c++) {
            float4 v = *(const float4*)(xb + (long)c * HW + 4 * p4);
            acc.x += v.x * v.x; acc.y += v.y * v.y;
            acc.z += v.z * v.z; acc.w += v.w * v.w;
        }
        s4[t] = acc;
        __syncthreads();
        if (t < P4) {
            float4 r = s4[t];
            for (int k = 1; k < nstr; k++) {
                float4 v = s4[t + k * P4];
                r.x += v.x; r.y += v.y; r.z += v.z; r.w += v.w;
            }
            *(float4*)&sP[4 * t] = r;
        }
        __syncthreads();
        for (int p = t; p < HW; p += 1024) {
            int py = p / W, px = p - py * W;
            float s = 0.0f;
            for (int dy = -1; dy <= 1; dy++) {
                int qy = py + dy;
                if (qy < 0 || qy >= W) continue;
                for (int dx = -1; dx <= 1; dx++) {
                    int qx = px + dx;
                    if (qx < 0 || qx >= W) continue;
                    s += sP[qy * W + qx];
                }
            }
            dst[b * HW + p] = 1.0f / fmaxf(sqrtf(s), 1e-12f);
        }
    } else if (bid == 12) {
        for (int o = t; o < 4096; o += 1024) {
            { // scale 4 (n = 1024)
                float src = (o + 0.5f) / 4.0f - 0.5f;
                float f = floorf(src);
                float tt = src - f;
                int fi = (int)f;
                int4 id; float4 w;
                id.x = min(max(fi - 1, 0), 1023); id.y = min(max(fi, 0), 1023);
                id.z = min(max(fi + 1, 0), 1023); id.w = min(max(fi + 2, 0), 1023);
                w.x = cubic_w(tt + 1.0f); w.y = cubic_w(tt);
                w.z = cubic_w(tt - 1.0f); w.w = cubic_w(tt - 2.0f);
                g_i4[o] = id; g_w4[o] = w;
            }
            { // scale 16 (n = 256)
                float src = (o + 0.5f) / 16.0f - 0.5f;
                float f = floorf(src);
                float tt = src - f;
                int fi = (int)f;
                int4 id; float4 w;
                id.x = min(max(fi - 1, 0), 255); id.y = min(max(fi, 0), 255);
                id.z = min(max(fi + 1, 0), 255); id.w = min(max(fi + 2, 0), 255);
                w.x = cubic_w(tt + 1.0f); w.y = cubic_w(tt);
                w.z = cubic_w(tt - 1.0f); w.w = cubic_w(tt - 2.0f);
                g_i16[o] = id; g_w16[o] = w;
            }
        }
    } else {
        for (int o = t; o < 8192; o += 1024) g_key[o] = 0ull;
    }
}

// ---------------------------------------------------------------------------
// CHW -> HWC transpose.  grid (HW/32, C/32, B), block (32,8)
// ---------------------------------------------------------------------------
__global__ void transpose_kernel(const float* __restrict__ src, float* __restrict__ dst,
                                 int C, int HW)
{
    __shared__ float tile[32][33];
    int b = blockIdx.z;
    int hw0 = blockIdx.x * 32, c0 = blockIdx.y * 32;
    const float* s = src + (long)b * C * HW;
    float* d = dst + (long)b * HW * C;
    #pragma unroll
    for (int j = 0; j < 4; j++)
        tile[threadIdx.y + 8 * j][threadIdx.x] =
            s[(long)(c0 + threadIdx.y + 8 * j) * HW + hw0 + threadIdx.x];
    __syncthreads();
    #pragma unroll
    for (int j = 0; j < 4; j++)
        d[(long)(hw0 + threadIdx.y + 8 * j) * C + c0 + threadIdx.x] =
            tile[threadIdx.x][threadIdx.y + 8 * j];
}

// ---------------------------------------------------------------------------
// Big Gram GEMM (lv3, K=64, W=64) with fused dx-diag epilogue + FFMA2 core.
// 128x128 tile, 256 thr, 8x8/thread.  sG aliases As/Bs (epilogue-only).
// Per-batch launch (b arg).
// ---------------------------------------------------------------------------
#define GB_SMEM (128 * 132 * 4)

__global__ void __launch_bounds__(256) gram_big_kernel(
    const float* __restrict__ A, const float* __restrict__ B,
    float* __restrict__ H, int b)
{
    const int N = 4096, K = 64, W = 64;
    extern __shared__ float sh[];
    float* As = sh;                 // [16][128]
    float* Bs = sh + 16 * 128;      // [16][128]
    float* sG = sh;                 // [128][132]  (reused after mainloop)

    const float* Ab = A + (long)b * K * N;
    const float* Bb = B + (long)b * K * N;
    float* Hb = H + (long)b * N * N;

    int t = threadIdx.x;
    int tx = t & 15, ty = t >> 4;
    int i0 = blockIdx.y * 128, j0 = blockIdx.x * 128;
    int lr = t >> 5;             // 0..7
    int lc = (t & 31) * 4;       // 0..124

    unsigned long long acc2[8][4];
    #pragma unroll
    for (int u = 0; u < 8; u++)
        #pragma unroll
        for (int v = 0; v < 4; v++) acc2[u][v] = 0ull;

    #pragma unroll
    for (int k0 = 0; k0 < K; k0 += 16) {
        *(float4*)&As[lr * 128 + lc]       = *(const float4*)&Ab[(long)(k0 + lr) * N + i0 + lc];
        *(float4*)&As[(lr + 8) * 128 + lc] = *(const float4*)&Ab[(long)(k0 + lr + 8) * N + i0 + lc];
        *(float4*)&Bs[lr * 128 + lc]       = *(const float4*)&Bb[(long)(k0 + lr) * N + j0 + lc];
        *(float4*)&Bs[(lr + 8) * 128 + lc] = *(const float4*)&Bb[(long)(k0 + lr + 8) * N + j0 + lc];
        __syncthreads();
        #pragma unroll
        for (int kk = 0; kk < 16; kk++) {
            float4 a0 = *(float4*)&As[kk * 128 + ty * 8];
            float4 a1 = *(float4*)&As[kk * 128 + ty * 8 + 4];
            float4 b0 = *(float4*)&Bs[kk * 128 + tx * 8];
            float4 b1 = *(float4*)&Bs[kk * 128 + tx * 8 + 4];
            unsigned long long av[8];
            av[0] = pack2(a0.x, a0.x); av[1] = pack2(a0.y, a0.y);
            av[2] = pack2(a0.z, a0.z); av[3] = pack2(a0.w, a0.w);
            av[4] = pack2(a1.x, a1.x); av[5] = pack2(a1.y, a1.y);
            av[6] = pack2(a1.z, a1.z); av[7] = pack2(a1.w, a1.w);
            unsigned long long bp[4];
            bp[0] = pack2(b0.x, b0.y); bp[1] = pack2(b0.z, b0.w);
            bp[2] = pack2(b1.x, b1.y); bp[3] = pack2(b1.z, b1.w);
            #pragma unroll
            for (int u = 0; u < 8; u++)
                #pragma unroll
                for (int v = 0; v < 4; v++)
                    ffma2(acc2[u][v], av[u], bp[v]);
        }
        __syncthreads();
    }

    // stage into sG (stride 132) — aliases As/Bs, safe after final sync above
    #pragma unroll
    for (int u = 0; u < 8; u++) {
        int r = ty * 8 + u;
        float2 p0 = unpack2(acc2[u][0]);
        float2 p1 = unpack2(acc2[u][1]);
        float2 p2 = unpack2(acc2[u][2]);
        float2 p3 = unpack2(acc2[u][3]);
        *(float4*)&sG[r * 132 + tx * 8]     = make_float4(p0.x, p0.y, p1.x, p1.y);
        *(float4*)&sG[r * 132 + tx * 8 + 4] = make_float4(p2.x, p2.y, p3.x, p3.y);
    }
    __syncthreads();

    const int wm = W - 1;
    #pragma unroll
    for (int u = 0; u < 8; u++) {
        int r = ty * 8 + u;
        int ixm = r & wm;            // i0 multiple of 128, W | 128
        float vals[8];
        #pragma unroll
        for (int v = 0; v < 8; v++) {
            int c = tx * 8 + v;
            int jxm = c & wm;
            float x = sG[r * 132 + c];
            if (ixm > 0  && jxm > 0)  x += sG[(r - 1) * 132 + (c - 1)];
            if (ixm < wm && jxm < wm) x += sG[(r + 1) * 132 + (c + 1)];
            vals[v] = x;
        }
        long row = (long)(i0 + r) * N + j0 + tx * 8;
        *(float4*)&Hb[row]     = make_float4(vals[0], vals[1], vals[2], vals[3]);
        *(float4*)&Hb[row + 4] = make_float4(vals[4], vals[5], vals[6], vals[7]);
    }
}

// ---------------------------------------------------------------------------
// Small Gram GEMM (lv2): 64x64 tile, 4x4/thread, fused dx epilogue.
// ---------------------------------------------------------------------------
__global__ void __launch_bounds__(256) gram_small_kernel(
    const float* __restrict__ A, const float* __restrict__ B,
    float* __restrict__ H, int N, int K, int W)
{
    __shared__ float As[16 * 64];
    __shared__ float Bs[16 * 64];
    __shared__ float sG[64 * 68];

    int b = blockIdx.z;
    const float* Ab = A + (long)b * K * N;
    const float* Bb = B + (long)b * K * N;
    float* Hb = H + (long)b * N * N;

    int t = threadIdx.x;
    int tx = t & 15, ty = t >> 4;
    int i0 = blockIdx.y * 64, j0 = blockIdx.x * 64;
    int lr = t >> 4;             // 0..15
    int lc = (t & 15) * 4;       // 0..60

    float acc[4][4];
    #pragma unroll
    for (int u = 0; u < 4; u++)
        #pragma unroll
        for (int v = 0; v < 4; v++) acc[u][v] = 0.0f;

    for (int k0 = 0; k0 < K; k0 += 16) {
        *(float4*)&As[lr * 64 + lc] = *(const float4*)&Ab[(long)(k0 + lr) * N + i0 + lc];
        *(float4*)&Bs[lr * 64 + lc] = *(const float4*)&Bb[(long)(k0 + lr) * N + j0 + lc];
        __syncthreads();
        #pragma unroll
        for (int kk = 0; kk < 16; kk++) {
            float4 a0 = *(float4*)&As[kk * 64 + ty * 4];
            float4 b0 = *(float4*)&Bs[kk * 64 + tx * 4];
            float a[4] = {a0.x, a0.y, a0.z, a0.w};
            float bb[4] = {b0.x, b0.y, b0.z, b0.w};
            #pragma unroll
            for (int u = 0; u < 4; u++)
                #pragma unroll
                for (int v = 0; v < 4; v++) acc[u][v] += a[u] * bb[v];
        }
        __syncthreads();
    }

    #pragma unroll
    for (int u = 0; u < 4; u++) {
        int r = ty * 4 + u;
        *(float4*)&sG[r * 68 + tx * 4] = make_float4(acc[u][0], acc[u][1], acc[u][2], acc[u][3]);
    }
    __syncthreads();

    int wm = W - 1;
    #pragma unroll
    for (int u = 0; u < 4; u++) {
        int r = ty * 4 + u;
        int ixm = r & wm;
        float vals[4];
        #pragma unroll
        for (int v = 0; v < 4; v++) {
            int c = tx * 4 + v;
            int jxm = c & wm;
            float x = sG[r * 68 + c];
            if (ixm > 0  && jxm > 0)  x += sG[(r - 1) * 68 + (c - 1)];
            if (ixm < wm && jxm < wm) x += sG[(r + 1) * 68 + (c + 1)];
            vals[v] = x;
        }
        long row = (long)(i0 + r) * N + j0 + tx * 4;
        *(float4*)&Hb[row] = make_float4(vals[0], vals[1], vals[2], vals[3]);
    }
}

// ---------------------------------------------------------------------------
// Tiny Gram GEMM (lv1: N=256, K=256, W=16): 32x32 tile, 2x2/thread -> 128 blocks
// ---------------------------------------------------------------------------
__global__ void __launch_bounds__(256) gram_tiny_kernel(
    const float* __restrict__ A, const float* __restrict__ B,
    float* __restrict__ H)
{
    const int N = 256, K = 256, W = 16;
    __shared__ float As[16 * 32];
    __shared__ float Bs[16 * 32];
    __shared__ float sG[32 * 36];

    int b = blockIdx.z;
    const float* Ab = A + (long)b * K * N;
    const float* Bb = B + (long)b * K * N;
    float* Hb = H + (long)b * N * N;

    int t = threadIdx.x;
    int tx = t & 15, ty = t >> 4;
    int i0 = blockIdx.y * 32, j0 = blockIdx.x * 32;
    int lr = t >> 4;             // 0..15
    int lc = (t & 15) * 2;       // 0..30

    float acc[2][2] = {{0.f, 0.f}, {0.f, 0.f}};

    for (int k0 = 0; k0 < K; k0 += 16) {
        *(float2*)&As[lr * 32 + lc] = *(const float2*)&Ab[(long)(k0 + lr) * N + i0 + lc];
        *(float2*)&Bs[lr * 32 + lc] = *(const float2*)&Bb[(long)(k0 + lr) * N + j0 + lc];
        __syncthreads();
        #pragma unroll
        for (int kk = 0; kk < 16; kk++) {
            float2 a0 = *(float2*)&As[kk * 32 + ty * 2];
            float2 b0 = *(float2*)&Bs[kk * 32 + tx * 2];
            acc[0][0] += a0.x * b0.x; acc[0][1] += a0.x * b0.y;
            acc[1][0] += a0.y * b0.x; acc[1][1] += a0.y * b0.y;
        }
        __syncthreads();
    }

    #pragma unroll
    for (int u = 0; u < 2; u++) {
        int r = ty * 2 + u;
        *(float2*)&sG[r * 36 + tx * 2] = make_float2(acc[u][0], acc[u][1]);
    }
    __syncthreads();

    const int wm = W - 1;
    #pragma unroll
    for (int u = 0; u < 2; u++) {
        int r = ty * 2 + u;
        int ixm = r & wm;
        float vals[2];
        #pragma unroll
        for (int v = 0; v < 2; v++) {
            int c = tx * 2 + v;
            int jxm = c & wm;
            float x = sG[r * 36 + c];
            if (ixm > 0  && jxm > 0)  x += sG[(r - 1) * 36 + (c - 1)];
            if (ixm < wm && jxm < wm) x += sG[(r + 1) * 36 + (c + 1)];
            vals[v] = x;
        }
        long row = (long)(i0 + r) * N + j0 + tx * 2;
        *(float2*)&Hb[row] = make_float2(vals[0], vals[1]);
    }
}

// ---------------------------------------------------------------------------
// dy-sum + normalize for lv2 (y < 1024) and lv1 (y >= 1024), one launch
// ---------------------------------------------------------------------------
__global__ void dynorm_both_kernel() {
    int b = blockIdx.z;
    int y = blockIdx.y;
    const float* Hh; float* R; const float* invR; const float* invL;
    int N, W, lw, i;
    if (y < 1024) { Hh = g_H2; R = g_R2; invR = g_invR2; invL = g_invL2; N = 1024; W = 32; lw = 5; i = y; }
    else          { Hh = g_H1; R = g_R1; invR = g_invR1; invL = g_invL1; N = 256;  W = 16; lw = 4; i = y - 1024; }
    int j = blockIdx.x * 256 + threadIdx.x;
    if (j >= N) return;
    long base = (long)b * N * N;
    const float* h = Hh + base;
    int iy = i >> lw, jy = j >> lw;
    float v = h[(long)i * N + j];
    if (iy > 0     && jy > 0)     v += h[(long)(i - W) * N + (j - W)];
    if (iy < W - 1 && jy < W - 1) v += h[(long)(i + W) * N + (j + W)];
    R[base + (long)i * N + j] = v * invR[b * N + i] * invL[b * N + j];
}

// ---------------------------------------------------------------------------
// Vertical bicubic upsample for both levels, one launch
// ---------------------------------------------------------------------------
__global__ void vup_both_kernel() {
    int b = blockIdx.z;
    int y = blockIdx.y;
    const float* R; float* V; const int4* idx; const float4* w; int Nin, io;
    if (y < 4096) { R = g_R2; V = g_R2v; idx = g_i4;  w = g_w4;  Nin = 1024; io = y; }
    else          { R = g_R1; V = g_R1v; idx = g_i16; w = g_w16; Nin = 256;  io = y - 4096; }
    int jc = blockIdx.x * 256 + threadIdx.x;
    if (jc >= Nin) return;
    const float* r = R + (long)b * Nin * Nin;
    int4 id = idx[io]; float4 ww = w[io];
    float v = ww.x * r[(long)id.x * Nin + jc]
            + ww.y * r[(long)id.y * Nin + jc]
            + ww.z * r[(long)id.z * Nin + jc]
            + ww.w * r[(long)id.w * Nin + jc];
    V[(long)b * 4096 * Nin + (long)io * Nin + jc] = v;
}

// ---------------------------------------------------------------------------
// Fused dy-sum(H3) + normalize + horizontal bicubic (5-tap windows, LDG —
// these are coalesced across tx) + split-i max/argmax.
// 4 cols/thread, 1024-col x 128-row blocks.  R13 body; per-batch launch.
// ---------------------------------------------------------------------------
__device__ __forceinline__ unsigned fkey_ord(float f) {
    unsigned u = __float_as_uint(f);
    return u ^ ((u >> 31) ? 0xFFFFFFFFu : 0x80000000u);
}
__device__ __forceinline__ unsigned long long pack_key(float v, int i) {
    return ((unsigned long long)fkey_ord(v) << 32) | (unsigned)(4095 - i);
}

__global__ void __launch_bounds__(256) fusedmax_kernel(int b) {
    int tx = threadIdx.x;
    int j0 = blockIdx.x * 1024 + tx * 4;
    int i0 = blockIdx.y * 128;

    const float* H  = g_H3  + (long)b * 4096 * 4096;
    const float* V2 = g_R2v + (long)b * 4096 * 1024;
    const float* V1 = g_R1v + (long)b * 4096 * 256;

    float4 iL = *(const float4*)&g_invL3[b * 4096 + j0];
    float iLv[4] = {iL.x, iL.y, iL.z, iL.w};
    int jy = j0 >> 6;
    bool jm = (jy > 0), jp = (jy < 63);

    int m2 = j0 >> 2;
    int o2[5], o1[5];
    #pragma unroll
    for (int o = 0; o < 5; o++) o2[o] = min(max(m2 - 2 + o, 0), 1023);
    int m1 = j0 >> 4;
    #pragma unroll
    for (int o = 0; o < 5; o++) o1[o] = min(max(m1 - 2 + o, 0), 255);
    int p1 = j0 & 15;
    int sel1[4];
    #pragma unroll
    for (int c = 0; c < 4; c++) sel1[c] = ((p1 + c) >= 8) ? 1 : 0;
    float4 w2[4], w1[4];
    #pragma unroll
    for (int c = 0; c < 4; c++) { w2[c] = g_w4[j0 + c]; w1[c] = g_w16[j0 + c]; }

    __shared__ float sR[128];
    if (tx < 128) sR[tx] = g_invR3[b * 4096 + i0 + tx];
    __syncthreads();

    float best[4] = {-1e30f, -1e30f, -1e30f, -1e30f};
    int bi[4] = {i0, i0, i0, i0};

    #pragma unroll 2
    for (int ii = 0; ii < 128; ii++) {
        int i = i0 + ii;
        int iy = i >> 6;
        const float* hrow = H + (long)i * 4096;
        float4 x = *(const float4*)(hrow + j0);
        float xv[4] = {x.x, x.y, x.z, x.w};
        if (iy > 0 && jm) {
            float4 d = *(const float4*)(hrow - (64 * 4096) + (j0 - 64));
            xv[0] += d.x; xv[1] += d.y; xv[2] += d.z; xv[3] += d.w;
        }
        if (iy < 63 && jp) {
            float4 d = *(const float4*)(hrow + (64 * 4096) + (j0 + 64));
            xv[0] += d.x; xv[1] += d.y; xv[2] += d.z; xv[3] += d.w;
        }
        float ir = sR[ii];
        #pragma unroll
        for (int c = 0; c < 4; c++) xv[c] = xv[c] * ir * iLv[c];

        const float* v2r = V2 + (long)i * 1024;
        float t2[5];
        #pragma unroll
        for (int o = 0; o < 5; o++) t2[o] = __ldg(v2r + o2[o]);
        const float* v1r = V1 + (long)i * 256;
        float t1[5];
        #pragma unroll
        for (int o = 0; o < 5; o++) t1[o] = __ldg(v1r + o1[o]);

        float s2[4];
        s2[0] = w2[0].x * t2[0] + w2[0].y * t2[1] + w2[0].z * t2[2] + w2[0].w * t2[3];
        s2[1] = w2[1].x * t2[0] + w2[1].y * t2[1] + w2[1].z * t2[2] + w2[1].w * t2[3];
        s2[2] = w2[2].x * t2[1] + w2[2].y * t2[2] + w2[2].z * t2[3] + w2[2].w * t2[4];
        s2[3] = w2[3].x * t2[1] + w2[3].y * t2[2] + w2[3].z * t2[3] + w2[3].w * t2[4];

        #pragma unroll
        for (int c = 0; c < 4; c++) {
            int s = sel1[c];
            float s1 = w1[c].x * t1[s] + w1[c].y * t1[s + 1] + w1[c].z * t1[s + 2] + w1[c].w * t1[s + 3];
            float xf = (xv[c] + s2[c]) + s1;
            if (xf > best[c]) { best[c] = xf; bi[c] = i; }
        }
    }
    #pragma unroll
    for (int c = 0; c < 4; c++)
        atomicMax(&g_key[b * 4096 + j0 + c], pack_key(best[c], bi[c]));
}

__global__ void decode_kernel(float* __restrict__ S, int b) {
    int t = blockIdx.x * blockDim.x + threadIdx.x;
    if (t >= 4096) return;
    int idx = b * 4096 + t;
    unsigned long long k = g_key[idx];
    unsigned hu = (unsigned)(k >> 32);
    unsigned u = (hu & 0x80000000u) ? (hu ^ 0x80000000u) : (hu ^ 0xFFFFFFFFu);
    S[idx] = __uint_as_float(u) / 3.0f;
    g_arg[idx] = 4095 - (int)(k & 0xFFFFFFFFu);
}

// ---------------------------------------------------------------------------
// Channel-coalesced gather+fold transfer on HWC refT.  Per-batch launch.
// grid (HH/32, C/32), block (8,32): tx = channel-group (4 ch), ty = pixel.
// ---------------------------------------------------------------------------
template<int S, int LOGH>
__global__ void __launch_bounds__(256) transfer_kernel(
    const float* __restrict__ refT, float* __restrict__ out, int C, int b)
{
    const int Hh = 1 << LOGH;
    const int HH = Hh * Hh;
    int p = blockIdx.x * 32 + threadIdx.y;
    int c0 = blockIdx.y * 32 + threadIdx.x * 4;

    int y = p >> LOGH, x = p & (Hh - 1);
    int yq = y / S, xq = x / S;
    int ym = y - yq * S, xm = x - xq * S;
    int ybase = yq + 1, xbase = xq + 1;
    const int* ab = g_arg + b * 4096;

    long off[9];
    #pragma unroll
    for (int dy = 0; dy < 3; dy++) {
        #pragma unroll
        for (int dx = 0; dx < 3; dx++) {
            int k = dy * 3 + dx;
            off[k] = -1;
            int ho = ybase - dy, wo = xbase - dx;
            if (ho >= 0 && ho < 64 && wo >= 0 && wo < 64) {
                int a = ab[ho * 64 + wo];
                int ryq = (a >> 6) + dy - 1;
                int rxq = (a & 63) + dx - 1;
                if (ryq >= 0 && ryq < 64 && rxq >= 0 && rxq < 64) {
                    int ry = S * ryq + ym, rx = S * rxq + xm;
                    off[k] = (long)(ry * Hh + rx) * C + c0;
                }
            }
        }
    }
    const float* rb = refT + (long)b * HH * C;
    float a0 = 0.f, a1 = 0.f, a2 = 0.f, a3 = 0.f;
    #pragma unroll
    for (int k = 0; k < 9; k++) {
        if (off[k] >= 0) {
            float4 v = *(const float4*)(rb + off[k]);
            a0 += v.x; a1 += v.y; a2 += v.z; a3 += v.w;
        }
    }
    long ob = ((long)b * C + c0) * HH + p;
    out[ob]          = a0 / 9.0f;
    out[ob + HH]     = a1 / 9.0f;
    out[ob + 2 * HH] = a2 / 9.0f;
    out[ob + 3 * HH] = a3 / 9.0f;
}

// ---------------------------------------------------------------------------
// Launch — two symmetric per-batch pipelines (R13 kernel bodies).
//   stream 0:  prep -> lv2/lv1 chain -> vup | fmax(b0) -> dec(b0) -> xfer(b0)
//   stream A:  gram(b0), gram(b1) | fmax(b1) -> dec(b1) -> xfer(b1)
//   stream B:  transposes (both batches)
// ---------------------------------------------------------------------------
static void* symaddr(const void* sym) {
    void* p = nullptr;
    cudaGetSymbolAddress(&p, sym);
    return p;
}

extern "C" void kernel_launch(void* const* d_in, const int* in_sizes, int n_in,
                              void* d_out, int out_size)
{
    const float* lrsr1  = (const float*)d_in[0];   // (2,256,16,16)
    const float* lrsr2  = (const float*)d_in[1];   // (2,128,32,32)
    const float* lrsr3  = (const float*)d_in[2];   // (2,64,64,64)
    const float* refsr1 = (const float*)d_in[3];
    const float* refsr2 = (const float*)d_in[4];
    const float* refsr3 = (const float*)d_in[5];
    const float* ref1   = (const float*)d_in[6];   // (2,64,256,256)
    const float* ref2   = (const float*)d_in[7];   // (2,128,128,128)
    const float* ref3   = (const float*)d_in[8];   // (2,256,64,64)

    float* out = (float*)d_out;
    float* S  = out;                         // 2*4096
    float* T3 = S + 2 * 4096;                // 2*256*64*64
    float* T2 = T3 + 2L * 256 * 64 * 64;     // 2*128*128*128
    float* T1 = T2 + 2L * 128 * 128 * 128;   // 2*64*256*256

    float* pH3 = (float*)symaddr(g_H3);
    float* pH2 = (float*)symaddr(g_H2);
    float* pH1 = (float*)symaddr(g_H1);
    float* pT3 = (float*)symaddr(g_T3);
    float* pT2 = (float*)symaddr(g_T2);
    float* pT1 = (float*)symaddr(g_T1);

    cudaFuncSetAttribute(gram_big_kernel,
                         cudaFuncAttributeMaxDynamicSharedMemorySize, GB_SMEM);

    static cudaStream_t sA = nullptr, sB = nullptr;
    static cudaEvent_t evFork = nullptr, evB0 = nullptr, evVup = nullptr,
                       evTrans = nullptr, evADone = nullptr;
    if (sA == nullptr) {
        cudaStreamCreateWithFlags(&sA, cudaStreamNonBlocking);
        cudaStreamCreateWithFlags(&sB, cudaStreamNonBlocking);
        cudaEventCreateWithFlags(&evFork, cudaEventDisableTiming);
        cudaEventCreateWithFlags(&evB0, cudaEventDisableTiming);
        cudaEventCreateWithFlags(&evVup, cudaEventDisableTiming);
        cudaEventCreateWithFlags(&evTrans, cudaEventDisableTiming);
        cudaEventCreateWithFlags(&evADone, cudaEventDisableTiming);
    }

    // Fork
    cudaEventRecord(evFork, 0);
    cudaStreamWaitEvent(sA, evFork, 0);
    cudaStreamWaitEvent(sB, evFork, 0);

    // Stream A: lv3 Grams per batch (FMA-bound)
    gram_big_kernel<<<dim3(32, 32), 256, GB_SMEM, sA>>>(refsr3, lrsr3, pH3, 0);
    cudaEventRecord(evB0, sA);
    gram_big_kernel<<<dim3(32, 32), 256, GB_SMEM, sA>>>(refsr3, lrsr3, pH3, 1);

    // Stream B: CHW -> HWC transposes (DRAM-bound)
    transpose_kernel<<<dim3(128, 8, 2),  dim3(32, 8), 0, sB>>>(ref3, pT3, 256, 4096);
    transpose_kernel<<<dim3(512, 4, 2),  dim3(32, 8), 0, sB>>>(ref2, pT2, 128, 16384);
    transpose_kernel<<<dim3(2048, 2, 2), dim3(32, 8), 0, sB>>>(ref1, pT1, 64, 65536);
    cudaEventRecord(evTrans, sB);

    // Stream 0: prep -> lv2/lv1 pyramid -> vup   (also resets g_key)
    prep_kernel<<<14, 1024>>>(lrsr3, refsr3, lrsr2, refsr2, lrsr1, refsr1);
    gram_small_kernel<<<dim3(16, 16, 2), 256>>>(refsr2, lrsr2, pH2, 1024, 128, 32);
    gram_tiny_kernel<<<dim3(8, 8, 2), 256>>>(refsr1, lrsr1, pH1);
    dynorm_both_kernel<<<dim3(4, 1280, 2), 256>>>();
    vup_both_kernel<<<dim3(4, 8192, 2), 256>>>();
    cudaEventRecord(evVup, 0);

    // Pipeline b0 on stream 0 (needs gram(b0) + vup)
    cudaStreamWaitEvent(0, evB0, 0);
    fusedmax_kernel<<<dim3(4, 32), 256>>>(0);
    decode_kernel<<<16, 256>>>(S, 0);
    cudaStreamWaitEvent(0, evTrans, 0);
    transfer_kernel<1, 6><<<dim3(128, 8),  dim3(8, 32)>>>(pT3, T3, 256, 0);
    transfer_kernel<2, 7><<<dim3(512, 4),  dim3(8, 32)>>>(pT2, T2, 128, 0);
    transfer_kernel<4, 8><<<dim3(2048, 2), dim3(8, 32)>>>(pT1, T1, 64, 0);

    // Pipeline b1 on stream A (needs gram(b1) [stream order] + vup + transposes)
    cudaStreamWaitEvent(sA, evVup, 0);
    fusedmax_kernel<<<dim3(4, 32), 256, 0, sA>>>(1);
    decode_kernel<<<16, 256, 0, sA>>>(S, 1);
    cudaStreamWaitEvent(sA, evTrans, 0);
    transfer_kernel<1, 6><<<dim3(128, 8),  dim3(8, 32), 0, sA>>>(pT3, T3, 256, 1);
    transfer_kernel<2, 7><<<dim3(512, 4),  dim3(8, 32), 0, sA>>>(pT2, T2, 128, 1);
    transfer_kernel<4, 8><<<dim3(2048, 2), dim3(8, 32), 0, sA>>>(pT1, T1, 64, 1);
    cudaEventRecord(evADone, sA);

    // Join everything back to the capture stream
    cudaStreamWaitEvent(0, evADone, 0);
}

// round 17
// speedup vs baseline: 1.3024x; 1.0734x over previous
#include <cuda_runtime.h>
#include <cuda_bf16.h>
#include <cstdint>
#include <math.h>

// ---------------------------------------------------------------------------
// Static device scratch (no allocation allowed)
// ---------------------------------------------------------------------------
__device__ __align__(128) float g_H3[2u * 4096u * 4096u];   // 134 MB (dx-summed Gram lv3)
__device__ __align__(128) float g_H2[2u * 1024u * 1024u];
__device__ __align__(128) float g_H1[2u * 256u * 256u];
__device__ __align__(128) float g_R2[2u * 1024u * 1024u];
__device__ __align__(128) float g_R1[2u * 256u * 256u];
__device__ __align__(128) float g_R2v[2u * 4096u * 1024u];  // vertical x4 of R2
__device__ __align__(128) float g_R1v[2u * 4096u * 256u];   // vertical x16 of R1
__device__ __align__(128) float g_T3[2u * 4096u * 256u];    // ref3 in HWC
__device__ __align__(128) float g_T2[2u * 16384u * 128u];   // ref2 in HWC
__device__ __align__(128) float g_T1[2u * 65536u * 64u];    // ref1 in HWC
__device__ __align__(128) float g_invL3[2 * 4096];
__device__ __align__(128) float g_invR3[2 * 4096];
__device__ __align__(128) float g_invL2[2 * 1024];
__device__ __align__(128) float g_invR2[2 * 1024];
__device__ __align__(128) float g_invL1[2 * 256];
__device__ __align__(128) float g_invR1[2 * 256];
__device__ __align__(128) int4   g_i4[4096];
__device__ __align__(128) float4 g_w4[4096];
__device__ __align__(128) int4   g_i16[4096];
__device__ __align__(128) float4 g_w16[4096];
__device__ __align__(128) unsigned long long g_key[2 * 4096];
__device__ __align__(128) int g_arg[2 * 4096];

// ---------------------------------------------------------------------------
// Packed f32x2 FMA helpers (sm_103a; 2 independent IEEE rn FMAs per instr)
// ---------------------------------------------------------------------------
__device__ __forceinline__ unsigned long long pack2(float lo, float hi) {
    unsigned long long r;
    asm("mov.b64 %0, {%1, %2};" : "=l"(r) : "f"(lo), "f"(hi));
    return r;
}
__device__ __forceinline__ void ffma2(unsigned long long& d,
                                      unsigned long long a, unsigned long long b) {
    asm("fma.rn.f32x2 %0, %1, %2, %0;" : "+l"(d) : "l"(a), "l"(b));
}
__device__ __forceinline__ float2 unpack2(unsigned long long v) {
    float lo, hi;
    asm("mov.b64 {%0, %1}, %2;" : "=f"(lo), "=f"(hi) : "l"(v));
    return make_float2(lo, hi);
}

// ---------------------------------------------------------------------------
// Bicubic weight (PyTorch a=-0.75)
// ---------------------------------------------------------------------------
__device__ __forceinline__ float cubic_w(float x) {
    const float a = -0.75f;
    float ax = fabsf(x);
    float ax2 = ax * ax, ax3 = ax2 * ax;
    float w1 = (a + 2.0f) * ax3 - (a + 3.0f) * ax2 + 1.0f;
    float w2 = ((a * ax3 - 5.0f * a * ax2) + 8.0f * a * ax) - 4.0f * a;
    return (ax <= 1.0f) ? w1 : ((ax < 2.0f) ? w2 : 0.0f);
}

// ---------------------------------------------------------------------------
// prep: block 0..11 -> sumsq + 3x3 zero-pad box norm for 6 tensor-batches
//       block 12    -> bicubic tables,  block 13 -> argmax key reset
// ---------------------------------------------------------------------------
__global__ void __launch_bounds__(1024) prep_kernel(
    const float* __restrict__ lrsr3, const float* __restrict__ refsr3,
    const float* __restrict__ lrsr2, const float* __restrict__ refsr2,
    const float* __restrict__ lrsr1, const float* __restrict__ refsr1)
{
    int bid = blockIdx.x;
    int t = threadIdx.x;
    if (bid < 12) {
        int ti = bid >> 1, b = bid & 1;
        const float* src; float* dst; int C, W;
        switch (ti) {
            case 0: src = lrsr3;  dst = g_invL3; C = 64;  W = 64; break;
            case 1: src = refsr3; dst = g_invR3; C = 64;  W = 64; break;
            case 2: src = lrsr2;  dst = g_invL2; C = 128; W = 32; break;
            case 3: src = refsr2; dst = g_invR2; C = 128; W = 32; break;
            case 4: src = lrsr1;  dst = g_invL1; C = 256; W = 16; break;
            default:src = refsr1; dst = g_invR1; C = 256; W = 16; break;
        }
        int HW = W * W, P4 = HW >> 2;
        int nstr = 1024 / P4;                 // 1, 4, 16
        int cper = C / nstr;                  // 64, 32, 16
        __shared__ float4 s4[1024];
        __shared__ float sP[4096];
        int p4 = t & (P4 - 1), st = t / P4;
        const float* xb = src + (long)b * C * HW;
        float4 acc = make_float4(0.f, 0.f, 0.f, 0.f);
        int cs = st * cper;
        for (int c = cs; c < cs + cper; c++) {
            float4 v = *(const float4*)(xb + (long)c * HW + 4 * p4);
            acc.x += v.x * v.x; acc.y += v.y * v.y;
            acc.z += v.z * v.z; acc.w += v.w * v.w;
        }
        s4[t] = acc;
        __syncthreads();
        if (t < P4) {
            float4 r = s4[t];
            for (int k = 1; k < nstr; k++) {
                float4 v = s4[t + k * P4];
                r.x += v.x; r.y += v.y; r.z += v.z; r.w += v.w;
            }
            *(float4*)&sP[4 * t] = r;
        }
        __syncthreads();
        for (int p = t; p < HW; p += 1024) {
            int py = p / W, px = p - py * W;
            float s = 0.0f;
            for (int dy = -1; dy <= 1; dy++) {
                int qy = py + dy;
                if (qy < 0 || qy >= W) continue;
                for (int dx = -1; dx <= 1; dx++) {
                    int qx = px + dx;
                    if (qx < 0 || qx >= W) continue;
                    s += sP[qy * W + qx];
                }
            }
            dst[b * HW + p] = 1.0f / fmaxf(sqrtf(s), 1e-12f);
        }
    } else if (bid == 12) {
        for (int o = t; o < 4096; o += 1024) {
            { // scale 4 (n = 1024)
                float src = (o + 0.5f) / 4.0f - 0.5f;
                float f = floorf(src);
                float tt = src - f;
                int fi = (int)f;
                int4 id; float4 w;
                id.x = min(max(fi - 1, 0), 1023); id.y = min(max(fi, 0), 1023);
                id.z = min(max(fi + 1, 0), 1023); id.w = min(max(fi + 2, 0), 1023);
                w.x = cubic_w(tt + 1.0f); w.y = cubic_w(tt);
                w.z = cubic_w(tt - 1.0f); w.w = cubic_w(tt - 2.0f);
                g_i4[o] = id; g_w4[o] = w;
            }
            { // scale 16 (n = 256)
                float src = (o + 0.5f) / 16.0f - 0.5f;
                float f = floorf(src);
                float tt = src - f;
                int fi = (int)f;
                int4 id; float4 w;
                id.x = min(max(fi - 1, 0), 255); id.y = min(max(fi, 0), 255);
                id.z = min(max(fi + 1, 0), 255); id.w = min(max(fi + 2, 0), 255);
                w.x = cubic_w(tt + 1.0f); w.y = cubic_w(tt);
                w.z = cubic_w(tt - 1.0f); w.w = cubic_w(tt - 2.0f);
                g_i16[o] = id; g_w16[o] = w;
            }
        }
    } else {
        for (int o = t; o < 8192; o += 1024) g_key[o] = 0ull;
    }
}

// ---------------------------------------------------------------------------
// CHW -> HWC transpose.  grid (HW/32, C/32, B), block (32,8)
// ---------------------------------------------------------------------------
__global__ void transpose_kernel(const float* __restrict__ src, float* __restrict__ dst,
                                 int C, int HW)
{
    __shared__ float tile[32][33];
    int b = blockIdx.z;
    int hw0 = blockIdx.x * 32, c0 = blockIdx.y * 32;
    const float* s = src + (long)b * C * HW;
    float* d = dst + (long)b * HW * C;
    #pragma unroll
    for (int j = 0; j < 4; j++)
        tile[threadIdx.y + 8 * j][threadIdx.x] =
            s[(long)(c0 + threadIdx.y + 8 * j) * HW + hw0 + threadIdx.x];
    __syncthreads();
    #pragma unroll
    for (int j = 0; j < 4; j++)
        d[(long)(hw0 + threadIdx.y + 8 * j) * C + c0 + threadIdx.x] =
            tile[threadIdx.x][threadIdx.y + 8 * j];
}

// ---------------------------------------------------------------------------
// Big Gram GEMM (lv3, K=64, W=64) with fused dx-diag epilogue + FFMA2 core.
// 128x128 tile, 256 thr, 8x8/thread.  sG aliases As/Bs (epilogue-only).
// Per-batch + per-row-slab launch (b, ybase args).
// ---------------------------------------------------------------------------
#define GB_SMEM (128 * 132 * 4)

__global__ void __launch_bounds__(256) gram_big_kernel(
    const float* __restrict__ A, const float* __restrict__ B,
    float* __restrict__ H, int b, int ybase)
{
    const int N = 4096, K = 64, W = 64;
    extern __shared__ float sh[];
    float* As = sh;                 // [16][128]
    float* Bs = sh + 16 * 128;      // [16][128]
    float* sG = sh;                 // [128][132]  (reused after mainloop)

    const float* Ab = A + (long)b * K * N;
    const float* Bb = B + (long)b * K * N;
    float* Hb = H + (long)b * N * N;

    int t = threadIdx.x;
    int tx = t & 15, ty = t >> 4;
    int i0 = (ybase + blockIdx.y) * 128, j0 = blockIdx.x * 128;
    int lr = t >> 5;             // 0..7
    int lc = (t & 31) * 4;       // 0..124

    unsigned long long acc2[8][4];
    #pragma unroll
    for (int u = 0; u < 8; u++)
        #pragma unroll
        for (int v = 0; v < 4; v++) acc2[u][v] = 0ull;

    #pragma unroll
    for (int k0 = 0; k0 < K; k0 += 16) {
        *(float4*)&As[lr * 128 + lc]       = *(const float4*)&Ab[(long)(k0 + lr) * N + i0 + lc];
        *(float4*)&As[(lr + 8) * 128 + lc] = *(const float4*)&Ab[(long)(k0 + lr + 8) * N + i0 + lc];
        *(float4*)&Bs[lr * 128 + lc]       = *(const float4*)&Bb[(long)(k0 + lr) * N + j0 + lc];
        *(float4*)&Bs[(lr + 8) * 128 + lc] = *(const float4*)&Bb[(long)(k0 + lr + 8) * N + j0 + lc];
        __syncthreads();
        #pragma unroll
        for (int kk = 0; kk < 16; kk++) {
            float4 a0 = *(float4*)&As[kk * 128 + ty * 8];
            float4 a1 = *(float4*)&As[kk * 128 + ty * 8 + 4];
            float4 b0 = *(float4*)&Bs[kk * 128 + tx * 8];
            float4 b1 = *(float4*)&Bs[kk * 128 + tx * 8 + 4];
            unsigned long long av[8];
            av[0] = pack2(a0.x, a0.x); av[1] = pack2(a0.y, a0.y);
            av[2] = pack2(a0.z, a0.z); av[3] = pack2(a0.w, a0.w);
            av[4] = pack2(a1.x, a1.x); av[5] = pack2(a1.y, a1.y);
            av[6] = pack2(a1.z, a1.z); av[7] = pack2(a1.w, a1.w);
            unsigned long long bp[4];
            bp[0] = pack2(b0.x, b0.y); bp[1] = pack2(b0.z, b0.w);
            bp[2] = pack2(b1.x, b1.y); bp[3] = pack2(b1.z, b1.w);
            #pragma unroll
            for (int u = 0; u < 8; u++)
                #pragma unroll
                for (int v = 0; v < 4; v++)
                    ffma2(acc2[u][v], av[u], bp[v]);
        }
        __syncthreads();
    }

    // stage into sG (stride 132) — aliases As/Bs, safe after final sync above
    #pragma unroll
    for (int u = 0; u < 8; u++) {
        int r = ty * 8 + u;
        float2 p0 = unpack2(acc2[u][0]);
        float2 p1 = unpack2(acc2[u][1]);
        float2 p2 = unpack2(acc2[u][2]);
        float2 p3 = unpack2(acc2[u][3]);
        *(float4*)&sG[r * 132 + tx * 8]     = make_float4(p0.x, p0.y, p1.x, p1.y);
        *(float4*)&sG[r * 132 + tx * 8 + 4] = make_float4(p2.x, p2.y, p3.x, p3.y);
    }
    __syncthreads();

    const int wm = W - 1;
    #pragma unroll
    for (int u = 0; u < 8; u++) {
        int r = ty * 8 + u;
        int ixm = r & wm;            // i0 multiple of 128, W | 128
        float vals[8];
        #pragma unroll
        for (int v = 0; v < 8; v++) {
            int c = tx * 8 + v;
            int jxm = c & wm;
            float x = sG[r * 132 + c];
            if (ixm > 0  && jxm > 0)  x += sG[(r - 1) * 132 + (c - 1)];
            if (ixm < wm && jxm < wm) x += sG[(r + 1) * 132 + (c + 1)];
            vals[v] = x;
        }
        long row = (long)(i0 + r) * N + j0 + tx * 8;
        *(float4*)&Hb[row]     = make_float4(vals[0], vals[1], vals[2], vals[3]);
        *(float4*)&Hb[row + 4] = make_float4(vals[4], vals[5], vals[6], vals[7]);
    }
}

// ---------------------------------------------------------------------------
// Small Gram GEMM (lv2): 64x64 tile, 4x4/thread, fused dx epilogue.
// ---------------------------------------------------------------------------
__global__ void __launch_bounds__(256) gram_small_kernel(
    const float* __restrict__ A, const float* __restrict__ B,
    float* __restrict__ H, int N, int K, int W)
{
    __shared__ float As[16 * 64];
    __shared__ float Bs[16 * 64];
    __shared__ float sG[64 * 68];

    int b = blockIdx.z;
    const float* Ab = A + (long)b * K * N;
    const float* Bb = B + (long)b * K * N;
    float* Hb = H + (long)b * N * N;

    int t = threadIdx.x;
    int tx = t & 15, ty = t >> 4;
    int i0 = blockIdx.y * 64, j0 = blockIdx.x * 64;
    int lr = t >> 4;             // 0..15
    int lc = (t & 15) * 4;       // 0..60

    float acc[4][4];
    #pragma unroll
    for (int u = 0; u < 4; u++)
        #pragma unroll
        for (int v = 0; v < 4; v++) acc[u][v] = 0.0f;

    for (int k0 = 0; k0 < K; k0 += 16) {
        *(float4*)&As[lr * 64 + lc] = *(const float4*)&Ab[(long)(k0 + lr) * N + i0 + lc];
        *(float4*)&Bs[lr * 64 + lc] = *(const float4*)&Bb[(long)(k0 + lr) * N + j0 + lc];
        __syncthreads();
        #pragma unroll
        for (int kk = 0; kk < 16; kk++) {
            float4 a0 = *(float4*)&As[kk * 64 + ty * 4];
            float4 b0 = *(float4*)&Bs[kk * 64 + tx * 4];
            float a[4] = {a0.x, a0.y, a0.z, a0.w};
            float bb[4] = {b0.x, b0.y, b0.z, b0.w};
            #pragma unroll
            for (int u = 0; u < 4; u++)
                #pragma unroll
                for (int v = 0; v < 4; v++) acc[u][v] += a[u] * bb[v];
        }
        __syncthreads();
    }

    #pragma unroll
    for (int u = 0; u < 4; u++) {
        int r = ty * 4 + u;
        *(float4*)&sG[r * 68 + tx * 4] = make_float4(acc[u][0], acc[u][1], acc[u][2], acc[u][3]);
    }
    __syncthreads();

    int wm = W - 1;
    #pragma unroll
    for (int u = 0; u < 4; u++) {
        int r = ty * 4 + u;
        int ixm = r & wm;
        float vals[4];
        #pragma unroll
        for (int v = 0; v < 4; v++) {
            int c = tx * 4 + v;
            int jxm = c & wm;
            float x = sG[r * 68 + c];
            if (ixm > 0  && jxm > 0)  x += sG[(r - 1) * 68 + (c - 1)];
            if (ixm < wm && jxm < wm) x += sG[(r + 1) * 68 + (c + 1)];
            vals[v] = x;
        }
        long row = (long)(i0 + r) * N + j0 + tx * 4;
        *(float4*)&Hb[row] = make_float4(vals[0], vals[1], vals[2], vals[3]);
    }
}

// ---------------------------------------------------------------------------
// Tiny Gram GEMM (lv1: N=256, K=256, W=16): 32x32 tile, 2x2/thread -> 128 blocks
// ---------------------------------------------------------------------------
__global__ void __launch_bounds__(256) gram_tiny_kernel(
    const float* __restrict__ A, const float* __restrict__ B,
    float* __restrict__ H)
{
    const int N = 256, K = 256, W = 16;
    __shared__ float As[16 * 32];
    __shared__ float Bs[16 * 32];
    __shared__ float sG[32 * 36];

    int b = blockIdx.z;
    const float* Ab = A + (long)b * K * N;
    const float* Bb = B + (long)b * K * N;
    float* Hb = H + (long)b * N * N;

    int t = threadIdx.x;
    int tx = t & 15, ty = t >> 4;
    int i0 = blockIdx.y * 32, j0 = blockIdx.x * 32;
    int lr = t >> 4;             // 0..15
    int lc = (t & 15) * 2;       // 0..30

    float acc[2][2] = {{0.f, 0.f}, {0.f, 0.f}};

    for (int k0 = 0; k0 < K; k0 += 16) {
        *(float2*)&As[lr * 32 + lc] = *(const float2*)&Ab[(long)(k0 + lr) * N + i0 + lc];
        *(float2*)&Bs[lr * 32 + lc] = *(const float2*)&Bb[(long)(k0 + lr) * N + j0 + lc];
        __syncthreads();
        #pragma unroll
        for (int kk = 0; kk < 16; kk++) {
            float2 a0 = *(float2*)&As[kk * 32 + ty * 2];
            float2 b0 = *(float2*)&Bs[kk * 32 + tx * 2];
            acc[0][0] += a0.x * b0.x; acc[0][1] += a0.x * b0.y;
            acc[1][0] += a0.y * b0.x; acc[1][1] += a0.y * b0.y;
        }
        __syncthreads();
    }

    #pragma unroll
    for (int u = 0; u < 2; u++) {
        int r = ty * 2 + u;
        *(float2*)&sG[r * 36 + tx * 2] = make_float2(acc[u][0], acc[u][1]);
    }
    __syncthreads();

    const int wm = W - 1;
    #pragma unroll
    for (int u = 0; u < 2; u++) {
        int r = ty * 2 + u;
        int ixm = r & wm;
        float vals[2];
        #pragma unroll
        for (int v = 0; v < 2; v++) {
            int c = tx * 2 + v;
            int jxm = c & wm;
            float x = sG[r * 36 + c];
            if (ixm > 0  && jxm > 0)  x += sG[(r - 1) * 36 + (c - 1)];
            if (ixm < wm && jxm < wm) x += sG[(r + 1) * 36 + (c + 1)];
            vals[v] = x;
        }
        long row = (long)(i0 + r) * N + j0 + tx * 2;
        *(float2*)&Hb[row] = make_float2(vals[0], vals[1]);
    }
}

// ---------------------------------------------------------------------------
// dy-sum + normalize for lv2 (y < 1024) and lv1 (y >= 1024), one launch
// ---------------------------------------------------------------------------
__global__ void dynorm_both_kernel() {
    int b = blockIdx.z;
    int y = blockIdx.y;
    const float* Hh; float* R; const float* invR; const float* invL;
    int N, W, lw, i;
    if (y < 1024) { Hh = g_H2; R = g_R2; invR = g_invR2; invL = g_invL2; N = 1024; W = 32; lw = 5; i = y; }
    else          { Hh = g_H1; R = g_R1; invR = g_invR1; invL = g_invL1; N = 256;  W = 16; lw = 4; i = y - 1024; }
    int j = blockIdx.x * 256 + threadIdx.x;
    if (j >= N) return;
    long base = (long)b * N * N;
    const float* h = Hh + base;
    int iy = i >> lw, jy = j >> lw;
    float v = h[(long)i * N + j];
    if (iy > 0     && jy > 0)     v += h[(long)(i - W) * N + (j - W)];
    if (iy < W - 1 && jy < W - 1) v += h[(long)(i + W) * N + (j + W)];
    R[base + (long)i * N + j] = v * invR[b * N + i] * invL[b * N + j];
}

// ---------------------------------------------------------------------------
// Vertical bicubic upsample for both levels, one launch
// ---------------------------------------------------------------------------
__global__ void vup_both_kernel() {
    int b = blockIdx.z;
    int y = blockIdx.y;
    const float* R; float* V; const int4* idx; const float4* w; int Nin, io;
    if (y < 4096) { R = g_R2; V = g_R2v; idx = g_i4;  w = g_w4;  Nin = 1024; io = y; }
    else          { R = g_R1; V = g_R1v; idx = g_i16; w = g_w16; Nin = 256;  io = y - 4096; }
    int jc = blockIdx.x * 256 + threadIdx.x;
    if (jc >= Nin) return;
    const float* r = R + (long)b * Nin * Nin;
    int4 id = idx[io]; float4 ww = w[io];
    float v = ww.x * r[(long)id.x * Nin + jc]
            + ww.y * r[(long)id.y * Nin + jc]
            + ww.z * r[(long)id.z * Nin + jc]
            + ww.w * r[(long)id.w * Nin + jc];
    V[(long)b * 4096 * Nin + (long)io * Nin + jc] = v;
}

// ---------------------------------------------------------------------------
// Fused dy-sum(H3) + normalize + horizontal bicubic + split-i max/argmax.
// 4 cols/thread, 1024-col x 128-row blocks.  Per-batch + i-group launch.
// ---------------------------------------------------------------------------
__device__ __forceinline__ unsigned fkey_ord(float f) {
    unsigned u = __float_as_uint(f);
    return u ^ ((u >> 31) ? 0xFFFFFFFFu : 0x80000000u);
}
__device__ __forceinline__ unsigned long long pack_key(float v, int i) {
    return ((unsigned long long)fkey_ord(v) << 32) | (unsigned)(4095 - i);
}

__global__ void __launch_bounds__(256) fusedmax_kernel(int b, int ibase) {
    int tx = threadIdx.x;
    int j0 = blockIdx.x * 1024 + tx * 4;
    int i0 = (ibase + blockIdx.y) * 128;

    const float* H  = g_H3  + (long)b * 4096 * 4096;
    const float* V2 = g_R2v + (long)b * 4096 * 1024;
    const float* V1 = g_R1v + (long)b * 4096 * 256;

    float4 iL = *(const float4*)&g_invL3[b * 4096 + j0];
    float iLv[4] = {iL.x, iL.y, iL.z, iL.w};
    int jy = j0 >> 6;
    bool jm = (jy > 0), jp = (jy < 63);

    int m2 = j0 >> 2;
    int o2[5], o1[5];
    #pragma unroll
    for (int o = 0; o < 5; o++) o2[o] = min(max(m2 - 2 + o, 0), 1023);
    int m1 = j0 >> 4;
    #pragma unroll
    for (int o = 0; o < 5; o++) o1[o] = min(max(m1 - 2 + o, 0), 255);
    int p1 = j0 & 15;
    int sel1[4];
    #pragma unroll
    for (int c = 0; c < 4; c++) sel1[c] = ((p1 + c) >= 8) ? 1 : 0;
    float4 w2[4], w1[4];
    #pragma unroll
    for (int c = 0; c < 4; c++) { w2[c] = g_w4[j0 + c]; w1[c] = g_w16[j0 + c]; }

    __shared__ float sR[128];
    if (tx < 128) sR[tx] = g_invR3[b * 4096 + i0 + tx];
    __syncthreads();

    float best[4] = {-1e30f, -1e30f, -1e30f, -1e30f};
    int bi[4] = {i0, i0, i0, i0};

    #pragma unroll 2
    for (int ii = 0; ii < 128; ii++) {
        int i = i0 + ii;
        int iy = i >> 6;
        const float* hrow = H + (long)i * 4096;
        float4 x = *(const float4*)(hrow + j0);
        float xv[4] = {x.x, x.y, x.z, x.w};
        if (iy > 0 && jm) {
            float4 d = *(const float4*)(hrow - (64 * 4096) + (j0 - 64));
            xv[0] += d.x; xv[1] += d.y; xv[2] += d.z; xv[3] += d.w;
        }
        if (iy < 63 && jp) {
            float4 d = *(const float4*)(hrow + (64 * 4096) + (j0 + 64));
            xv[0] += d.x; xv[1] += d.y; xv[2] += d.z; xv[3] += d.w;
        }
        float ir = sR[ii];
        #pragma unroll
        for (int c = 0; c < 4; c++) xv[c] = xv[c] * ir * iLv[c];

        const float* v2r = V2 + (long)i * 1024;
        float t2[5];
        #pragma unroll
        for (int o = 0; o < 5; o++) t2[o] = __ldg(v2r + o2[o]);
        const float* v1r = V1 + (long)i * 256;
        float t1[5];
        #pragma unroll
        for (int o = 0; o < 5; o++) t1[o] = __ldg(v1r + o1[o]);

        float s2[4];
        s2[0] = w2[0].x * t2[0] + w2[0].y * t2[1] + w2[0].z * t2[2] + w2[0].w * t2[3];
        s2[1] = w2[1].x * t2[0] + w2[1].y * t2[1] + w2[1].z * t2[2] + w2[1].w * t2[3];
        s2[2] = w2[2].x * t2[1] + w2[2].y * t2[2] + w2[2].z * t2[3] + w2[2].w * t2[4];
        s2[3] = w2[3].x * t2[1] + w2[3].y * t2[2] + w2[3].z * t2[3] + w2[3].w * t2[4];

        #pragma unroll
        for (int c = 0; c < 4; c++) {
            int s = sel1[c];
            float s1 = w1[c].x * t1[s] + w1[c].y * t1[s + 1] + w1[c].z * t1[s + 2] + w1[c].w * t1[s + 3];
            float xf = (xv[c] + s2[c]) + s1;
            if (xf > best[c]) { best[c] = xf; bi[c] = i; }
        }
    }
    #pragma unroll
    for (int c = 0; c < 4; c++)
        atomicMax(&g_key[b * 4096 + j0 + c], pack_key(best[c], bi[c]));
}

__global__ void decode_kernel(float* __restrict__ S, int b) {
    int t = blockIdx.x * blockDim.x + threadIdx.x;
    if (t >= 4096) return;
    int idx = b * 4096 + t;
    unsigned long long k = g_key[idx];
    unsigned hu = (unsigned)(k >> 32);
    unsigned u = (hu & 0x80000000u) ? (hu ^ 0x80000000u) : (hu ^ 0xFFFFFFFFu);
    S[idx] = __uint_as_float(u) / 3.0f;
    g_arg[idx] = 4095 - (int)(k & 0xFFFFFFFFu);
}

// ---------------------------------------------------------------------------
// Channel-coalesced gather+fold transfer on HWC refT.  Per-batch launch.
// grid (HH/32, C/32), block (8,32): tx = channel-group (4 ch), ty = pixel.
// ---------------------------------------------------------------------------
template<int S, int LOGH>
__global__ void __launch_bounds__(256) transfer_kernel(
    const float* __restrict__ refT, float* __restrict__ out, int C, int b)
{
    const int Hh = 1 << LOGH;
    const int HH = Hh * Hh;
    int p = blockIdx.x * 32 + threadIdx.y;
    int c0 = blockIdx.y * 32 + threadIdx.x * 4;

    int y = p >> LOGH, x = p & (Hh - 1);
    int yq = y / S, xq = x / S;
    int ym = y - yq * S, xm = x - xq * S;
    int ybase = yq + 1, xbase = xq + 1;
    const int* ab = g_arg + b * 4096;

    long off[9];
    #pragma unroll
    for (int dy = 0; dy < 3; dy++) {
        #pragma unroll
        for (int dx = 0; dx < 3; dx++) {
            int k = dy * 3 + dx;
            off[k] = -1;
            int ho = ybase - dy, wo = xbase - dx;
            if (ho >= 0 && ho < 64 && wo >= 0 && wo < 64) {
                int a = ab[ho * 64 + wo];
                int ryq = (a >> 6) + dy - 1;
                int rxq = (a & 63) + dx - 1;
                if (ryq >= 0 && ryq < 64 && rxq >= 0 && rxq < 64) {
                    int ry = S * ryq + ym, rx = S * rxq + xm;
                    off[k] = (long)(ry * Hh + rx) * C + c0;
                }
            }
        }
    }
    const float* rb = refT + (long)b * HH * C;
    float a0 = 0.f, a1 = 0.f, a2 = 0.f, a3 = 0.f;
    #pragma unroll
    for (int k = 0; k < 9; k++) {
        if (off[k] >= 0) {
            float4 v = *(const float4*)(rb + off[k]);
            a0 += v.x; a1 += v.y; a2 += v.z; a3 += v.w;
        }
    }
    long ob = ((long)b * C + c0) * HH + p;
    out[ob]          = a0 / 9.0f;
    out[ob + HH]     = a1 / 9.0f;
    out[ob + 2 * HH] = a2 / 9.0f;
    out[ob + 3 * HH] = a3 / 9.0f;
}

// ---------------------------------------------------------------------------
// Launch — per-batch pipelines with row-slab gram->fmax pipelining.
//   sA:  gram(b0,s0) gram(b0,s1) gram(b1,s0) gram(b1,s1)   [slab events]
//   s0:  prep -> lv2/lv1 -> vup | fmaxA(b0) fmaxB(b0) dec(b0) xfer(b0)
//   sB:  transposes | fmaxA(b1) fmaxB(b1) dec(b1) xfer(b1)
// fmaxA = i-blocks 0..14 (needs slab0 only: rows <= 128*14+191 = 1983 < 2048)
// fmaxB = i-blocks 15..31 (needs slab1)
// ---------------------------------------------------------------------------
static void* symaddr(const void* sym) {
    void* p = nullptr;
    cudaGetSymbolAddress(&p, sym);
    return p;
}

extern "C" void kernel_launch(void* const* d_in, const int* in_sizes, int n_in,
                              void* d_out, int out_size)
{
    const float* lrsr1  = (const float*)d_in[0];   // (2,256,16,16)
    const float* lrsr2  = (const float*)d_in[1];   // (2,128,32,32)
    const float* lrsr3  = (const float*)d_in[2];   // (2,64,64,64)
    const float* refsr1 = (const float*)d_in[3];
    const float* refsr2 = (const float*)d_in[4];
    const float* refsr3 = (const float*)d_in[5];
    const float* ref1   = (const float*)d_in[6];   // (2,64,256,256)
    const float* ref2   = (const float*)d_in[7];   // (2,128,128,128)
    const float* ref3   = (const float*)d_in[8];   // (2,256,64,64)

    float* out = (float*)d_out;
    float* S  = out;                         // 2*4096
    float* T3 = S + 2 * 4096;                // 2*256*64*64
    float* T2 = T3 + 2L * 256 * 64 * 64;     // 2*128*128*128
    float* T1 = T2 + 2L * 128 * 128 * 128;   // 2*64*256*256

    float* pH3 = (float*)symaddr(g_H3);
    float* pH2 = (float*)symaddr(g_H2);
    float* pH1 = (float*)symaddr(g_H1);
    float* pT3 = (float*)symaddr(g_T3);
    float* pT2 = (float*)symaddr(g_T2);
    float* pT1 = (float*)symaddr(g_T1);

    cudaFuncSetAttribute(gram_big_kernel,
                         cudaFuncAttributeMaxDynamicSharedMemorySize, GB_SMEM);

    static cudaStream_t sA = nullptr, sB = nullptr;
    static cudaEvent_t evFork = nullptr, evVup = nullptr, evTrans = nullptr,
                       evADone = nullptr, evBDone = nullptr;
    static cudaEvent_t evSlab[4] = {nullptr, nullptr, nullptr, nullptr};
    if (sA == nullptr) {
        cudaStreamCreateWithFlags(&sA, cudaStreamNonBlocking);
        cudaStreamCreateWithFlags(&sB, cudaStreamNonBlocking);
        cudaEventCreateWithFlags(&evFork, cudaEventDisableTiming);
        cudaEventCreateWithFlags(&evVup, cudaEventDisableTiming);
        cudaEventCreateWithFlags(&evTrans, cudaEventDisableTiming);
        cudaEventCreateWithFlags(&evADone, cudaEventDisableTiming);
        cudaEventCreateWithFlags(&evBDone, cudaEventDisableTiming);
        for (int s = 0; s < 4; s++)
            cudaEventCreateWithFlags(&evSlab[s], cudaEventDisableTiming);
    }

    // Fork
    cudaEventRecord(evFork, 0);
    cudaStreamWaitEvent(sA, evFork, 0);
    cudaStreamWaitEvent(sB, evFork, 0);

    // Stream A: lv3 Grams per batch, 2 row-slabs each (FMA-bound)
    gram_big_kernel<<<dim3(32, 16), 256, GB_SMEM, sA>>>(refsr3, lrsr3, pH3, 0, 0);
    cudaEventRecord(evSlab[0], sA);
    gram_big_kernel<<<dim3(32, 16), 256, GB_SMEM, sA>>>(refsr3, lrsr3, pH3, 0, 16);
    cudaEventRecord(evSlab[1], sA);
    gram_big_kernel<<<dim3(32, 16), 256, GB_SMEM, sA>>>(refsr3, lrsr3, pH3, 1, 0);
    cudaEventRecord(evSlab[2], sA);
    gram_big_kernel<<<dim3(32, 16), 256, GB_SMEM, sA>>>(refsr3, lrsr3, pH3, 1, 16);
    cudaEventRecord(evSlab[3], sA);

    // Stream B: CHW -> HWC transposes (DRAM-bound)
    transpose_kernel<<<dim3(128, 8, 2),  dim3(32, 8), 0, sB>>>(ref3, pT3, 256, 4096);
    transpose_kernel<<<dim3(512, 4, 2),  dim3(32, 8), 0, sB>>>(ref2, pT2, 128, 16384);
    transpose_kernel<<<dim3(2048, 2, 2), dim3(32, 8), 0, sB>>>(ref1, pT1, 64, 65536);
    cudaEventRecord(evTrans, sB);

    // Stream 0: prep -> lv2/lv1 pyramid -> vup   (also resets g_key)
    prep_kernel<<<14, 1024>>>(lrsr3, refsr3, lrsr2, refsr2, lrsr1, refsr1);
    gram_small_kernel<<<dim3(16, 16, 2), 256>>>(refsr2, lrsr2, pH2, 1024, 128, 32);
    gram_tiny_kernel<<<dim3(8, 8, 2), 256>>>(refsr1, lrsr1, pH1);
    dynorm_both_kernel<<<dim3(4, 1280, 2), 256>>>();
    vup_both_kernel<<<dim3(4, 8192, 2), 256>>>();
    cudaEventRecord(evVup, 0);

    // Pipeline b0 on stream 0 (slab-pipelined fmax)
    cudaStreamWaitEvent(0, evSlab[0], 0);
    fusedmax_kernel<<<dim3(4, 15), 256>>>(0, 0);     // i-blocks 0..14
    cudaStreamWaitEvent(0, evSlab[1], 0);
    fusedmax_kernel<<<dim3(4, 17), 256>>>(0, 15);    // i-blocks 15..31
    decode_kernel<<<16, 256>>>(S, 0);
    cudaStreamWaitEvent(0, evTrans, 0);
    transfer_kernel<1, 6><<<dim3(128, 8),  dim3(8, 32)>>>(pT3, T3, 256, 0);
    transfer_kernel<2, 7><<<dim3(512, 4),  dim3(8, 32)>>>(pT2, T2, 128, 0);
    transfer_kernel<4, 8><<<dim3(2048, 2), dim3(8, 32)>>>(pT1, T1, 64, 0);

    // Pipeline b1 on stream B (after transposes; slab-pipelined fmax)
    cudaStreamWaitEvent(sB, evVup, 0);
    cudaStreamWaitEvent(sB, evSlab[2], 0);
    fusedmax_kernel<<<dim3(4, 15), 256, 0, sB>>>(1, 0);
    cudaStreamWaitEvent(sB, evSlab[3], 0);
    fusedmax_kernel<<<dim3(4, 17), 256, 0, sB>>>(1, 15);
    decode_kernel<<<16, 256, 0, sB>>>(S, 1);
    transfer_kernel<1, 6><<<dim3(128, 8),  dim3(8, 32), 0, sB>>>(pT3, T3, 256, 1);
    transfer_kernel<2, 7><<<dim3(512, 4),  dim3(8, 32), 0, sB>>>(pT2, T2, 128, 1);
    transfer_kernel<4, 8><<<dim3(2048, 2), dim3(8, 32), 0, sB>>>(pT1, T1, 64, 1);
    cudaEventRecord(evBDone, sB);

    // Join everything back to the capture stream
    cudaStreamWaitEvent(0, evBDone, 0);
}